// round 10
// baseline (speedup 1.0000x reference)
#include <cuda_runtime.h>
#include <math.h>
#include <stdint.h>

#define T_DIM 4096
#define D_DIM 1024
#define H_NUM 16
#define C_DIM 64
#define GS   20   // gemm smem row stride (16 floats + 4 pad)

// Scratch (allocations forbidden -> device globals)
__device__ float g_qkv[T_DIM * 3 * D_DIM];   // [T][3*D]
__device__ float g_att[T_DIM * D_DIM];       // [T][D]

// ---------------------------------------------------------------------------
// helpers
// ---------------------------------------------------------------------------
__device__ __forceinline__ float tf32r(float x) {
    uint32_t y;
    asm("cvt.rna.tf32.f32 %0, %1;" : "=r"(y) : "f"(x));
    return __uint_as_float(y);
}
__device__ __forceinline__ void mma8(float* d, const uint32_t* a, const uint32_t* b) {
    asm volatile(
        "mma.sync.aligned.m16n8k8.row.col.f32.tf32.tf32.f32 "
        "{%0,%1,%2,%3}, {%4,%5,%6,%7}, {%8,%9}, {%0,%1,%2,%3};"
        : "+f"(d[0]), "+f"(d[1]), "+f"(d[2]), "+f"(d[3])
        : "r"(a[0]), "r"(a[1]), "r"(a[2]), "r"(a[3]), "r"(b[0]), "r"(b[1]));
}
__device__ __forceinline__ uint32_t asu(float x) { return __float_as_uint(x); }

// ===========================================================================
// mma.sync tf32 GEMM, 3xTF32 compensated (unchanged from R4/R7/R8, passing)
// ===========================================================================
__global__ void __launch_bounds__(256) gemm_mma_tf32x3(
    const float* __restrict__ A, const float* __restrict__ B, float* __restrict__ C,
    int M, int N, int K)
{
    __shared__ float sAh[128 * GS];
    __shared__ float sAl[128 * GS];
    __shared__ float sBh[128 * GS];
    __shared__ float sBl[128 * GS];

    const int tid  = threadIdx.x;
    const int lane = tid & 31;
    const int wid  = tid >> 5;
    const int wm   = wid >> 2;
    const int wn   = wid & 3;
    const int bm   = blockIdx.y * 128;
    const int bn   = blockIdx.x * 128;

    const int r0g = (tid + 0)   >> 2, c0g = ((tid + 0)   & 3) * 4;
    const int r1g = (tid + 256) >> 2, c1g = ((tid + 256) & 3) * 4;
    const float* A0 = A + (size_t)(bm + r0g) * K + c0g;
    const float* A1 = A + (size_t)(bm + r1g) * K + c1g;
    const float* B0 = B + (size_t)(bn + r0g) * K + c0g;
    const float* B1 = B + (size_t)(bn + r1g) * K + c1g;
    const int sa0 = r0g * GS + c0g, sa1 = r1g * GS + c1g;

    float acc[4][4][4];
#pragma unroll
    for (int i = 0; i < 4; i++)
#pragma unroll
        for (int j = 0; j < 4; j++)
#pragma unroll
            for (int k = 0; k < 4; k++) acc[i][j][k] = 0.f;

    const int nch = K >> 4;
    float4 ra0 = *(const float4*)A0, ra1 = *(const float4*)A1;
    float4 rb0 = *(const float4*)B0, rb1 = *(const float4*)B1;

    for (int c = 0; c < nch; c++) {
        {
            float4 h, l;
            h.x = tf32r(ra0.x); h.y = tf32r(ra0.y); h.z = tf32r(ra0.z); h.w = tf32r(ra0.w);
            l.x = tf32r(ra0.x - h.x); l.y = tf32r(ra0.y - h.y);
            l.z = tf32r(ra0.z - h.z); l.w = tf32r(ra0.w - h.w);
            *(float4*)&sAh[sa0] = h; *(float4*)&sAl[sa0] = l;
            h.x = tf32r(ra1.x); h.y = tf32r(ra1.y); h.z = tf32r(ra1.z); h.w = tf32r(ra1.w);
            l.x = tf32r(ra1.x - h.x); l.y = tf32r(ra1.y - h.y);
            l.z = tf32r(ra1.z - h.z); l.w = tf32r(ra1.w - h.w);
            *(float4*)&sAh[sa1] = h; *(float4*)&sAl[sa1] = l;
            h.x = tf32r(rb0.x); h.y = tf32r(rb0.y); h.z = tf32r(rb0.z); h.w = tf32r(rb0.w);
            l.x = tf32r(rb0.x - h.x); l.y = tf32r(rb0.y - h.y);
            l.z = tf32r(rb0.z - h.z); l.w = tf32r(rb0.w - h.w);
            *(float4*)&sBh[sa0] = h; *(float4*)&sBl[sa0] = l;
            h.x = tf32r(rb1.x); h.y = tf32r(rb1.y); h.z = tf32r(rb1.z); h.w = tf32r(rb1.w);
            l.x = tf32r(rb1.x - h.x); l.y = tf32r(rb1.y - h.y);
            l.z = tf32r(rb1.z - h.z); l.w = tf32r(rb1.w - h.w);
            *(float4*)&sBh[sa1] = h; *(float4*)&sBl[sa1] = l;
        }
        __syncthreads();

        if (c + 1 < nch) {
            const int off = (c + 1) * 16;
            ra0 = *(const float4*)(A0 + off); ra1 = *(const float4*)(A1 + off);
            rb0 = *(const float4*)(B0 + off); rb1 = *(const float4*)(B1 + off);
        }

#pragma unroll
        for (int ks = 0; ks < 2; ks++) {
            const int kc = ks * 8 + (lane & 3);
            uint32_t ah[4][4], al[4][4], bh[4][2], bl[4][2];
#pragma unroll
            for (int mt = 0; mt < 4; mt++) {
                const int r = (wm * 64 + mt * 16 + (lane >> 2)) * GS;
                ah[mt][0] = asu(sAh[r + kc]);          ah[mt][1] = asu(sAh[r + 8 * GS + kc]);
                ah[mt][2] = asu(sAh[r + kc + 4]);      ah[mt][3] = asu(sAh[r + 8 * GS + kc + 4]);
                al[mt][0] = asu(sAl[r + kc]);          al[mt][1] = asu(sAl[r + 8 * GS + kc]);
                al[mt][2] = asu(sAl[r + kc + 4]);      al[mt][3] = asu(sAl[r + 8 * GS + kc + 4]);
            }
#pragma unroll
            for (int nt = 0; nt < 4; nt++) {
                const int r = (wn * 32 + nt * 8 + (lane >> 2)) * GS;
                bh[nt][0] = asu(sBh[r + kc]); bh[nt][1] = asu(sBh[r + kc + 4]);
                bl[nt][0] = asu(sBl[r + kc]); bl[nt][1] = asu(sBl[r + kc + 4]);
            }
#pragma unroll
            for (int mt = 0; mt < 4; mt++)
#pragma unroll
                for (int nt = 0; nt < 4; nt++) {
                    mma8(acc[mt][nt], ah[mt], bh[nt]);
                    mma8(acc[mt][nt], ah[mt], bl[nt]);
                    mma8(acc[mt][nt], al[mt], bh[nt]);
                }
        }
        __syncthreads();
    }

#pragma unroll
    for (int mt = 0; mt < 4; mt++) {
        const int row = bm + wm * 64 + mt * 16 + (lane >> 2);
#pragma unroll
        for (int nt = 0; nt < 4; nt++) {
            const int col = bn + wn * 32 + nt * 8 + 2 * (lane & 3);
            *(float2*)&C[(size_t)row * N + col] =
                make_float2(acc[mt][nt][0], acc[mt][nt][1]);
            *(float2*)&C[(size_t)(row + 8) * N + col] =
                make_float2(acc[mt][nt][2], acc[mt][nt][3]);
        }
    }
}

// ---------------------------------------------------------------------------
// RoPE in place on q,k inside g_qkv [T][3*D]
// ---------------------------------------------------------------------------
__global__ void rope_kernel(float* __restrict__ qkv) {
    int idx = blockIdx.x * blockDim.x + threadIdx.x;
    if (idx >= T_DIM * H_NUM * (C_DIM / 2)) return;
    int t = idx >> 9;
    int r = idx & 511;
    int h = r >> 5;
    int p = r & 31;

    float inv_freq = expf(-(float)p * (logf(10000.0f) / 32.0f));
    float ang = (float)t * inv_freq;
    float s, c;
    sincosf(ang, &s, &c);

    size_t base_q = (size_t)t * (3 * D_DIM) + h * C_DIM + 2 * p;
    size_t base_k = base_q + D_DIM;

    float x1 = qkv[base_q], x2 = qkv[base_q + 1];
    qkv[base_q]     = x1 * c - x2 * s;
    qkv[base_q + 1] = x2 * c + x1 * s;

    float y1 = qkv[base_k], y2 = qkv[base_k + 1];
    qkv[base_k]     = y1 * c - y2 * s;
    qkv[base_k + 1] = y2 * c + y1 * s;
}

// ===========================================================================
// Tensor-core flash attention v3: hi/lo packed as float2 per element.
// Bq=128, Bk=64, C=64, 256 threads / 8 warps. 3xTF32 everywhere.
// Smem tiles (float2 {hi,lo}, row stride 68 float2 = 136 words ≡ 8 mod 32):
//   Qs[128][68], Ks[64][68], Vt[64][68] (V^T), Ps[128][68]  => 208,896 B
// Fragment loads are LDS.64 yielding hi AND lo together:
//   a-frag: 4 loads (was 16 scalar), b-frag: 2 loads/nt (was 8 scalar).
// All fragment load phases bank-conflict-free (banks 8g+2q distinct/phase).
// ===========================================================================
#define FR 68                                   // row stride in float2
#define FA_SMEM ((128 + 64 + 64 + 128) * FR * 8)
#define SC2 0.18033688f                         // 0.125 * log2(e)

__global__ void __launch_bounds__(256) flash_attn_tc(
    const float* __restrict__ qkv, float* __restrict__ out)
{
    extern __shared__ float2 sm2[];
    float2* Qs = sm2;                // [128][FR]
    float2* Ks = Qs + 128 * FR;      // [64][FR]
    float2* Vt = Ks + 64 * FR;       // [64][FR]  V^T: row=c, col=s
    float2* Ps = Vt + 64 * FR;       // [128][FR]

    const int h    = blockIdx.y;
    const int qb   = gridDim.x - 1 - blockIdx.x;   // big blocks first
    const int q0   = qb * 128;
    const int tid  = threadIdx.x;
    const int lane = tid & 31;
    const int wid  = tid >> 5;
    const int hcol = h * C_DIM;
    const int row0 = wid * 16 + (lane >> 2);       // local S/O row of c0,c1
    const int lq   = lane & 3;                     // quad index

    // loader mappings
    const int kr   = tid >> 4;          // K row base (idx=tid+256i -> row kr+16i)
    const int kc4  = (tid & 15) * 4;    // K col group
    const int vc   = tid & 63;          // V column (head dim c) -> V^T row
    const int vr4  = (tid >> 6) * 4;    // V s-chunk base

    // --- load Q tile [128][64] -> packed {h,l} ---
#pragma unroll
    for (int i = 0; i < 8; i++) {
        int idx = tid + 256 * i;
        int r = idx >> 4, c4 = (idx & 15) * 4;
        float4 v = *(const float4*)&qkv[(size_t)(q0 + r) * (3 * D_DIM) + hcol + c4];
        float hx = tf32r(v.x), hy = tf32r(v.y), hz = tf32r(v.z), hw = tf32r(v.w);
        float4* dst = (float4*)&Qs[r * FR + c4];
        dst[0] = make_float4(hx, tf32r(v.x - hx), hy, tf32r(v.y - hy));
        dst[1] = make_float4(hz, tf32r(v.z - hz), hw, tf32r(v.w - hw));
    }

    float m0 = -1e30f, m1 = -1e30f, l0 = 0.f, l1 = 0.f;
    float oacc[8][4];
#pragma unroll
    for (int nt = 0; nt < 8; nt++)
#pragma unroll
        for (int j = 0; j < 4; j++) oacc[nt][j] = 0.f;

    // prefetch registers for tile kb (K: 4 x float4, V: 16 scalars)
    float4 rk[4];
    float  rv[4][4];
    const float* kbase = qkv + 1024 + hcol + (size_t)kr * (3 * D_DIM) + kc4;
    const float* vbase = qkv + 2048 + hcol + vc;

    // prefetch kb = 0
#pragma unroll
    for (int i = 0; i < 4; i++)
        rk[i] = *(const float4*)(kbase + (size_t)(16 * i) * (3 * D_DIM));
#pragma unroll
    for (int i = 0; i < 4; i++)
#pragma unroll
        for (int j = 0; j < 4; j++)
            rv[i][j] = vbase[(size_t)(vr4 + 16 * i + j) * (3 * D_DIM)];

    const int kbmax = 2 * qb + 1;
    for (int kb = 0; kb <= kbmax; kb++) {
        __syncthreads();  // all warps done reading prior K/V smem

        // --- store prefetched tile to smem, packed {h,l} ---
#pragma unroll
        for (int i = 0; i < 4; i++) {
            const int r = kr + 16 * i;
            float4 kv = rk[i];
            float hx = tf32r(kv.x), hy = tf32r(kv.y), hz = tf32r(kv.z), hw = tf32r(kv.w);
            float4* kd = (float4*)&Ks[r * FR + kc4];
            kd[0] = make_float4(hx, tf32r(kv.x - hx), hy, tf32r(kv.y - hy));
            kd[1] = make_float4(hz, tf32r(kv.z - hz), hw, tf32r(kv.w - hw));

            float v0 = rv[i][0], v1 = rv[i][1], v2 = rv[i][2], v3 = rv[i][3];
            float h0 = tf32r(v0), h1 = tf32r(v1), h2 = tf32r(v2), h3 = tf32r(v3);
            float4* vd = (float4*)&Vt[vc * FR + vr4 + 16 * i];
            vd[0] = make_float4(h0, tf32r(v0 - h0), h1, tf32r(v1 - h1));
            vd[1] = make_float4(h2, tf32r(v2 - h2), h3, tf32r(v3 - h3));
        }
        __syncthreads();

        // --- prefetch tile kb+1 (hidden under compute below) ---
        if (kb < kbmax) {
            const size_t off = (size_t)(kb + 1) * 64 * (3 * D_DIM);
#pragma unroll
            for (int i = 0; i < 4; i++)
                rk[i] = *(const float4*)(kbase + off + (size_t)(16 * i) * (3 * D_DIM));
#pragma unroll
            for (int i = 0; i < 4; i++)
#pragma unroll
                for (int j = 0; j < 4; j++)
                    rv[i][j] = vbase[off + (size_t)(vr4 + 16 * i + j) * (3 * D_DIM)];
        }

        // --- S = Q K^T, 3xTF32 ---
        float sacc[8][4];
#pragma unroll
        for (int nt = 0; nt < 8; nt++)
#pragma unroll
            for (int j = 0; j < 4; j++) sacc[nt][j] = 0.f;

#pragma unroll
        for (int ks = 0; ks < 8; ks++) {
            const int kc = ks * 8 + lq;
            float2 a00 = Qs[row0 * FR + kc];
            float2 a01 = Qs[row0 * FR + kc + 4];
            float2 a10 = Qs[(row0 + 8) * FR + kc];
            float2 a11 = Qs[(row0 + 8) * FR + kc + 4];
            uint32_t ah[4] = { asu(a00.x), asu(a10.x), asu(a01.x), asu(a11.x) };
            uint32_t al[4] = { asu(a00.y), asu(a10.y), asu(a01.y), asu(a11.y) };
#pragma unroll
            for (int nt = 0; nt < 8; nt++) {
                const int br = (nt * 8 + (lane >> 2)) * FR;
                float2 b0 = Ks[br + kc];
                float2 b1 = Ks[br + kc + 4];
                uint32_t bh[2] = { asu(b0.x), asu(b1.x) };
                uint32_t bl[2] = { asu(b0.y), asu(b1.y) };
                mma8(sacc[nt], ah, bh);
                mma8(sacc[nt], ah, bl);
                mma8(sacc[nt], al, bh);
            }
        }

        // --- scale (log2 domain) + causal mask ---
        const bool mb = (kb >= 2 * qb);
        const int lim = q0 - kb * 64;   // keep col c if c <= row + lim
        float mx0 = -1e30f, mx1 = -1e30f;
#pragma unroll
        for (int nt = 0; nt < 8; nt++) {
            const int cb = nt * 8 + 2 * lq;
#pragma unroll
            for (int j = 0; j < 2; j++) {
                float v0 = sacc[nt][j] * SC2;
                float v1 = sacc[nt][2 + j] * SC2;
                if (mb) {
                    if (cb + j > row0 + lim)     v0 = -1e30f;
                    if (cb + j > row0 + 8 + lim) v1 = -1e30f;
                }
                sacc[nt][j] = v0; sacc[nt][2 + j] = v1;
                mx0 = fmaxf(mx0, v0); mx1 = fmaxf(mx1, v1);
            }
        }
        mx0 = fmaxf(mx0, __shfl_xor_sync(0xffffffffu, mx0, 1));
        mx0 = fmaxf(mx0, __shfl_xor_sync(0xffffffffu, mx0, 2));
        mx1 = fmaxf(mx1, __shfl_xor_sync(0xffffffffu, mx1, 1));
        mx1 = fmaxf(mx1, __shfl_xor_sync(0xffffffffu, mx1, 2));

        const float nm0 = fmaxf(m0, mx0), nm1 = fmaxf(m1, mx1);
        const float corr0 = exp2f(m0 - nm0), corr1 = exp2f(m1 - nm1);
        m0 = nm0; m1 = nm1;

        float rs0 = 0.f, rs1 = 0.f;
#pragma unroll
        for (int nt = 0; nt < 8; nt++) {
            const int cb = nt * 8 + 2 * lq;
            float p0 = exp2f(sacc[nt][0] - nm0);
            float p1 = exp2f(sacc[nt][1] - nm0);
            float p2 = exp2f(sacc[nt][2] - nm1);
            float p3 = exp2f(sacc[nt][3] - nm1);
            rs0 += p0 + p1; rs1 += p2 + p3;
            float h0 = tf32r(p0), h1 = tf32r(p1), h2 = tf32r(p2), h3 = tf32r(p3);
            *(float4*)&Ps[row0 * FR + cb] =
                make_float4(h0, tf32r(p0 - h0), h1, tf32r(p1 - h1));
            *(float4*)&Ps[(row0 + 8) * FR + cb] =
                make_float4(h2, tf32r(p2 - h2), h3, tf32r(p3 - h3));
        }
        rs0 += __shfl_xor_sync(0xffffffffu, rs0, 1);
        rs0 += __shfl_xor_sync(0xffffffffu, rs0, 2);
        rs1 += __shfl_xor_sync(0xffffffffu, rs1, 1);
        rs1 += __shfl_xor_sync(0xffffffffu, rs1, 2);
        l0 = l0 * corr0 + rs0;
        l1 = l1 * corr1 + rs1;

#pragma unroll
        for (int nt = 0; nt < 8; nt++) {
            oacc[nt][0] *= corr0; oacc[nt][1] *= corr0;
            oacc[nt][2] *= corr1; oacc[nt][3] *= corr1;
        }
        __syncwarp();   // P tile is warp-private (rows 16w..16w+15)

        // --- O += P V, 3xTF32 ---
#pragma unroll
        for (int ks = 0; ks < 8; ks++) {
            const int kc = ks * 8 + lq;
            float2 p00 = Ps[row0 * FR + kc];
            float2 p01 = Ps[row0 * FR + kc + 4];
            float2 p10 = Ps[(row0 + 8) * FR + kc];
            float2 p11 = Ps[(row0 + 8) * FR + kc + 4];
            uint32_t ph[4] = { asu(p00.x), asu(p10.x), asu(p01.x), asu(p11.x) };
            uint32_t pl[4] = { asu(p00.y), asu(p10.y), asu(p01.y), asu(p11.y) };
#pragma unroll
            for (int nt = 0; nt < 8; nt++) {
                const int br = (nt * 8 + (lane >> 2)) * FR;
                float2 b0 = Vt[br + kc];
                float2 b1 = Vt[br + kc + 4];
                uint32_t vh2[2] = { asu(b0.x), asu(b1.x) };
                uint32_t vl2[2] = { asu(b0.y), asu(b1.y) };
                mma8(oacc[nt], ph, vh2);
                mma8(oacc[nt], ph, vl2);
                mma8(oacc[nt], pl, vh2);
            }
        }
        __syncwarp();   // done reading warp-private P before next overwrite
    }

    // --- epilogue: normalize, store [T][D] ---
    const float inv0 = 1.0f / l0, inv1 = 1.0f / l1;
#pragma unroll
    for (int nt = 0; nt < 8; nt++) {
        const int cb = hcol + nt * 8 + 2 * lq;
        *(float2*)&out[(size_t)(q0 + row0) * D_DIM + cb] =
            make_float2(oacc[nt][0] * inv0, oacc[nt][1] * inv0);
        *(float2*)&out[(size_t)(q0 + row0 + 8) * D_DIM + cb] =
            make_float2(oacc[nt][2] * inv1, oacc[nt][3] * inv1);
    }
}

// ---------------------------------------------------------------------------
extern "C" void kernel_launch(void* const* d_in, const int* in_sizes, int n_in,
                              void* d_out, int out_size) {
    const float* x     = (const float*)d_in[0];  // [4096,1024]
    const float* Wqkv  = (const float*)d_in[1];  // [3072,1024]
    const float* Wproj = (const float*)d_in[2];  // [1024,1024]
    float* out = (float*)d_out;                  // [4096,1024]

    float* qkv; cudaGetSymbolAddress((void**)&qkv, g_qkv);
    float* att; cudaGetSymbolAddress((void**)&att, g_att);

    cudaFuncSetAttribute(flash_attn_tc, cudaFuncAttributeMaxDynamicSharedMemorySize, FA_SMEM);

    // 1) qkv = x @ W_qkv^T
    dim3 g1((3 * D_DIM) / 128, T_DIM / 128);
    gemm_mma_tf32x3<<<g1, 256>>>(x, Wqkv, qkv, T_DIM, 3 * D_DIM, D_DIM);

    // 2) RoPE in place on q, k
    int total = T_DIM * H_NUM * (C_DIM / 2);
    rope_kernel<<<(total + 255) / 256, 256>>>(qkv);

    // 3) causal flash attention (tensor cores, packed hi/lo) -> att [T][D]
    dim3 g2(T_DIM / 128, H_NUM);
    flash_attn_tc<<<g2, 256, FA_SMEM>>>(qkv, att);

    // 4) out = att @ W_proj^T
    dim3 g3(D_DIM / 128, T_DIM / 128);
    gemm_mma_tf32x3<<<g3, 256>>>(att, Wproj, out, T_DIM, D_DIM, D_DIM);
}

// round 11
// speedup vs baseline: 1.8276x; 1.8276x over previous
#include <cuda_runtime.h>
#include <cuda_bf16.h>
#include <math.h>
#include <stdint.h>

#define T_DIM 4096
#define D_DIM 1024
#define H_NUM 16
#define C_DIM 64
#define SP   12   // gemm plane row stride (8 bf16-pairs + 4 pad), uint32 units
#define FSP  36   // flash plane row stride (32 bf16-pairs + 4 pad), uint32 units

// Scratch (allocations forbidden -> device globals)
__device__ float g_qkv[T_DIM * 3 * D_DIM];   // [T][3*D]
__device__ float g_att[T_DIM * D_DIM];       // [T][D]

// ---------------------------------------------------------------------------
// helpers
// ---------------------------------------------------------------------------
__device__ __forceinline__ uint32_t bfpack(float a, float b) {
    __nv_bfloat162 t = __floats2bfloat162_rn(a, b);   // low half = a (k-even)
    return *(uint32_t*)&t;
}
// split (a,b) fp32 -> hi pair + lo pair (bf16x3 decomposition)
__device__ __forceinline__ void bfsplit2(float a, float b, uint32_t& hi, uint32_t& lo) {
    float ha = __bfloat162float(__float2bfloat16_rn(a));
    float hb = __bfloat162float(__float2bfloat16_rn(b));
    hi = bfpack(ha, hb);
    lo = bfpack(a - ha, b - hb);
}
__device__ __forceinline__ void mma16(float* d, const uint32_t* a, const uint32_t* b) {
    asm volatile(
        "mma.sync.aligned.m16n8k16.row.col.f32.bf16.bf16.f32 "
        "{%0,%1,%2,%3}, {%4,%5,%6,%7}, {%8,%9}, {%0,%1,%2,%3};"
        : "+f"(d[0]), "+f"(d[1]), "+f"(d[2]), "+f"(d[3])
        : "r"(a[0]), "r"(a[1]), "r"(a[2]), "r"(a[3]), "r"(b[0]), "r"(b[1]));
}

// ===========================================================================
// mma.sync bf16x3 GEMM: C[M,N] = A[M,K] * B[N,K]^T (fp32 io)
// 128x128 CTA tile, K-chunk 16 (one m16n8k16 step), 256 threads, 8 warps 64x32.
// hi/lo bf16-pair planes; fragment loads conflict-free at stride SP=12.
// Requires M%128==0, N%128==0, K%16==0.
// ===========================================================================
__global__ void __launch_bounds__(256) gemm_mma_bf16x3(
    const float* __restrict__ A, const float* __restrict__ B, float* __restrict__ C,
    int M, int N, int K)
{
    __shared__ uint32_t sAh[128 * SP];
    __shared__ uint32_t sAl[128 * SP];
    __shared__ uint32_t sBh[128 * SP];
    __shared__ uint32_t sBl[128 * SP];

    const int tid  = threadIdx.x;
    const int lane = tid & 31;
    const int g    = lane >> 2;    // group id
    const int tg   = lane & 3;     // thread in group
    const int wid  = tid >> 5;
    const int wm   = wid >> 2;
    const int wn   = wid & 3;
    const int bm   = blockIdx.y * 128;
    const int bn   = blockIdx.x * 128;

    // loader: 4 threads per row, 4 floats each (chunk = 16 floats/row)
    const int r0g = (tid + 0)   >> 2, c0g = ((tid + 0)   & 3) * 4;
    const int r1g = (tid + 256) >> 2, c1g = ((tid + 256) & 3) * 4;
    const float* A0 = A + (size_t)(bm + r0g) * K + c0g;
    const float* A1 = A + (size_t)(bm + r1g) * K + c1g;
    const float* B0 = B + (size_t)(bn + r0g) * K + c0g;
    const float* B1 = B + (size_t)(bn + r1g) * K + c1g;
    const int sa0 = r0g * SP + (c0g >> 1), sa1 = r1g * SP + (c1g >> 1);

    float acc[4][4][4];
#pragma unroll
    for (int i = 0; i < 4; i++)
#pragma unroll
        for (int j = 0; j < 4; j++)
#pragma unroll
            for (int k = 0; k < 4; k++) acc[i][j][k] = 0.f;

    const int nch = K >> 4;
    float4 ra0 = *(const float4*)A0, ra1 = *(const float4*)A1;
    float4 rb0 = *(const float4*)B0, rb1 = *(const float4*)B1;

    for (int c = 0; c < nch; c++) {
        {
            uint32_t h, l;
            bfsplit2(ra0.x, ra0.y, h, l); sAh[sa0]     = h; sAl[sa0]     = l;
            bfsplit2(ra0.z, ra0.w, h, l); sAh[sa0 + 1] = h; sAl[sa0 + 1] = l;
            bfsplit2(ra1.x, ra1.y, h, l); sAh[sa1]     = h; sAl[sa1]     = l;
            bfsplit2(ra1.z, ra1.w, h, l); sAh[sa1 + 1] = h; sAl[sa1 + 1] = l;
            bfsplit2(rb0.x, rb0.y, h, l); sBh[sa0]     = h; sBl[sa0]     = l;
            bfsplit2(rb0.z, rb0.w, h, l); sBh[sa0 + 1] = h; sBl[sa0 + 1] = l;
            bfsplit2(rb1.x, rb1.y, h, l); sBh[sa1]     = h; sBl[sa1]     = l;
            bfsplit2(rb1.z, rb1.w, h, l); sBh[sa1 + 1] = h; sBl[sa1 + 1] = l;
        }
        __syncthreads();

        if (c + 1 < nch) {
            const int off = (c + 1) * 16;
            ra0 = *(const float4*)(A0 + off); ra1 = *(const float4*)(A1 + off);
            rb0 = *(const float4*)(B0 + off); rb1 = *(const float4*)(B1 + off);
        }

        // one m16n8k16 step per chunk
        {
            uint32_t ah[4][4], al[4][4], bh[4][2], bl[4][2];
#pragma unroll
            for (int mt = 0; mt < 4; mt++) {
                const int r = (wm * 64 + mt * 16 + g) * SP;
                ah[mt][0] = sAh[r + tg];           ah[mt][1] = sAh[r + 8 * SP + tg];
                ah[mt][2] = sAh[r + tg + 4];       ah[mt][3] = sAh[r + 8 * SP + tg + 4];
                al[mt][0] = sAl[r + tg];           al[mt][1] = sAl[r + 8 * SP + tg];
                al[mt][2] = sAl[r + tg + 4];       al[mt][3] = sAl[r + 8 * SP + tg + 4];
            }
#pragma unroll
            for (int nt = 0; nt < 4; nt++) {
                const int r = (wn * 32 + nt * 8 + g) * SP;
                bh[nt][0] = sBh[r + tg];  bh[nt][1] = sBh[r + tg + 4];
                bl[nt][0] = sBl[r + tg];  bl[nt][1] = sBl[r + tg + 4];
            }
#pragma unroll
            for (int mt = 0; mt < 4; mt++)
#pragma unroll
                for (int nt = 0; nt < 4; nt++) {
                    mma16(acc[mt][nt], ah[mt], bh[nt]);
                    mma16(acc[mt][nt], ah[mt], bl[nt]);
                    mma16(acc[mt][nt], al[mt], bh[nt]);
                }
        }
        __syncthreads();
    }

#pragma unroll
    for (int mt = 0; mt < 4; mt++) {
        const int row = bm + wm * 64 + mt * 16 + g;
#pragma unroll
        for (int nt = 0; nt < 4; nt++) {
            const int col = bn + wn * 32 + nt * 8 + 2 * tg;
            *(float2*)&C[(size_t)row * N + col] =
                make_float2(acc[mt][nt][0], acc[mt][nt][1]);
            *(float2*)&C[(size_t)(row + 8) * N + col] =
                make_float2(acc[mt][nt][2], acc[mt][nt][3]);
        }
    }
}

// ---------------------------------------------------------------------------
// RoPE in place on q,k inside g_qkv [T][3*D]
// ---------------------------------------------------------------------------
__global__ void rope_kernel(float* __restrict__ qkv) {
    int idx = blockIdx.x * blockDim.x + threadIdx.x;
    if (idx >= T_DIM * H_NUM * (C_DIM / 2)) return;
    int t = idx >> 9;
    int r = idx & 511;
    int h = r >> 5;
    int p = r & 31;

    float inv_freq = expf(-(float)p * (logf(10000.0f) / 32.0f));
    float ang = (float)t * inv_freq;
    float s, c;
    sincosf(ang, &s, &c);

    size_t base_q = (size_t)t * (3 * D_DIM) + h * C_DIM + 2 * p;
    size_t base_k = base_q + D_DIM;

    float x1 = qkv[base_q], x2 = qkv[base_q + 1];
    qkv[base_q]     = x1 * c - x2 * s;
    qkv[base_q + 1] = x2 * c + x1 * s;

    float y1 = qkv[base_k], y2 = qkv[base_k + 1];
    qkv[base_k]     = y1 * c - y2 * s;
    qkv[base_k + 1] = y2 * c + y1 * s;
}

// ===========================================================================
// Tensor-core flash attention, bf16x3 (m16n8k16), causal.
// Bq=128, Bk=64, C=64, 256 threads / 8 warps (R8 structure, halved mma work).
// Planes (uint32 bf16-pairs, stride FSP=36: banks 4g+tg conflict-free):
//   Qh,Ql[128][36]  Kh,Kl[64][36]  Vth,Vtl[64][36] (V^T)  Ph,Pl[128][36]
//   => 110,592 B
// ===========================================================================
#define FA_SMEM ((2 * 128 + 2 * 64 + 2 * 64 + 2 * 128) * FSP * 4)
#define SC2 0.18033688f   // 0.125 * log2(e)

__global__ void __launch_bounds__(256) flash_attn_tc(
    const float* __restrict__ qkv, float* __restrict__ out)
{
    extern __shared__ uint32_t smu[];
    uint32_t* Qh  = smu;
    uint32_t* Ql  = Qh  + 128 * FSP;
    uint32_t* Kh  = Ql  + 128 * FSP;
    uint32_t* Kl  = Kh  + 64 * FSP;
    uint32_t* Vth = Kl  + 64 * FSP;   // V^T: row=c, pairs over s
    uint32_t* Vtl = Vth + 64 * FSP;
    uint32_t* Ph  = Vtl + 64 * FSP;
    uint32_t* Pl  = Ph  + 128 * FSP;

    const int h    = blockIdx.y;
    const int qb   = gridDim.x - 1 - blockIdx.x;   // big blocks first
    const int q0   = qb * 128;
    const int tid  = threadIdx.x;
    const int lane = tid & 31;
    const int g    = lane >> 2;
    const int tg   = lane & 3;
    const int wid  = tid >> 5;
    const int hcol = h * C_DIM;
    const int row0 = wid * 16 + g;                 // local S/O row of c0,c1

    // loader mappings
    const int kr   = tid >> 4;          // K/Q row base (idx=tid+256i -> row kr+16i)
    const int kc4  = (tid & 15) * 4;    // K/Q col group (4 floats = 2 pairs)
    const int vc   = tid & 63;          // V column (head dim c) -> V^T row
    const int vr4  = (tid >> 6) * 4;    // V s-chunk base

    // --- load Q tile [128][64], split to bf16 hi/lo pair planes ---
#pragma unroll
    for (int i = 0; i < 8; i++) {
        int idx = tid + 256 * i;
        int r = idx >> 4, c4 = (idx & 15) * 4;
        float4 v = *(const float4*)&qkv[(size_t)(q0 + r) * (3 * D_DIM) + hcol + c4];
        uint32_t hh, ll;
        int sa = r * FSP + (c4 >> 1);
        bfsplit2(v.x, v.y, hh, ll); Qh[sa]     = hh; Ql[sa]     = ll;
        bfsplit2(v.z, v.w, hh, ll); Qh[sa + 1] = hh; Ql[sa + 1] = ll;
    }

    float m0 = -1e30f, m1 = -1e30f, l0 = 0.f, l1 = 0.f;
    float oacc[8][4];
#pragma unroll
    for (int nt = 0; nt < 8; nt++)
#pragma unroll
        for (int j = 0; j < 4; j++) oacc[nt][j] = 0.f;

    // prefetch registers for tile kb (K: 4 x float4, V: 16 scalars)
    float4 rk[4];
    float  rv[4][4];
    const float* kbase = qkv + 1024 + hcol + (size_t)kr * (3 * D_DIM) + kc4;
    const float* vbase = qkv + 2048 + hcol + vc;

#pragma unroll
    for (int i = 0; i < 4; i++)
        rk[i] = *(const float4*)(kbase + (size_t)(16 * i) * (3 * D_DIM));
#pragma unroll
    for (int i = 0; i < 4; i++)
#pragma unroll
        for (int j = 0; j < 4; j++)
            rv[i][j] = vbase[(size_t)(vr4 + 16 * i + j) * (3 * D_DIM)];

    const int kbmax = 2 * qb + 1;
    for (int kb = 0; kb <= kbmax; kb++) {
        __syncthreads();  // all warps done reading prior K/V smem

        // --- store prefetched tile to smem planes ---
#pragma unroll
        for (int i = 0; i < 4; i++) {
            const int r = kr + 16 * i;
            float4 kv = rk[i];
            uint32_t hh, ll;
            int ka = r * FSP + (kc4 >> 1);
            bfsplit2(kv.x, kv.y, hh, ll); Kh[ka]     = hh; Kl[ka]     = ll;
            bfsplit2(kv.z, kv.w, hh, ll); Kh[ka + 1] = hh; Kl[ka + 1] = ll;

            int va = vc * FSP + ((vr4 + 16 * i) >> 1);
            bfsplit2(rv[i][0], rv[i][1], hh, ll); Vth[va]     = hh; Vtl[va]     = ll;
            bfsplit2(rv[i][2], rv[i][3], hh, ll); Vth[va + 1] = hh; Vtl[va + 1] = ll;
        }
        __syncthreads();

        // --- prefetch tile kb+1 (hidden under compute below) ---
        if (kb < kbmax) {
            const size_t off = (size_t)(kb + 1) * 64 * (3 * D_DIM);
#pragma unroll
            for (int i = 0; i < 4; i++)
                rk[i] = *(const float4*)(kbase + off + (size_t)(16 * i) * (3 * D_DIM));
#pragma unroll
            for (int i = 0; i < 4; i++)
#pragma unroll
                for (int j = 0; j < 4; j++)
                    rv[i][j] = vbase[off + (size_t)(vr4 + 16 * i + j) * (3 * D_DIM)];
        }

        // --- S = Q K^T, bf16x3 (4 k16 steps) ---
        float sacc[8][4];
#pragma unroll
        for (int nt = 0; nt < 8; nt++)
#pragma unroll
            for (int j = 0; j < 4; j++) sacc[nt][j] = 0.f;

#pragma unroll
        for (int ks = 0; ks < 4; ks++) {
            const int p0 = 8 * ks + tg;           // pair index of a0/b0
            const int ar = row0 * FSP;
            uint32_t ah[4], al[4];
            ah[0] = Qh[ar + p0];            ah[1] = Qh[ar + 8 * FSP + p0];
            ah[2] = Qh[ar + p0 + 4];        ah[3] = Qh[ar + 8 * FSP + p0 + 4];
            al[0] = Ql[ar + p0];            al[1] = Ql[ar + 8 * FSP + p0];
            al[2] = Ql[ar + p0 + 4];        al[3] = Ql[ar + 8 * FSP + p0 + 4];
#pragma unroll
            for (int nt = 0; nt < 8; nt++) {
                const int br = (nt * 8 + g) * FSP;
                uint32_t bh[2] = { Kh[br + p0], Kh[br + p0 + 4] };
                uint32_t bl[2] = { Kl[br + p0], Kl[br + p0 + 4] };
                mma16(sacc[nt], ah, bh);
                mma16(sacc[nt], ah, bl);
                mma16(sacc[nt], al, bh);
            }
        }

        // --- scale (log2 domain) + causal mask ---
        const bool mb = (kb >= 2 * qb);
        const int lim = q0 - kb * 64;   // keep col c if c <= row + lim
        float mx0 = -1e30f, mx1 = -1e30f;
#pragma unroll
        for (int nt = 0; nt < 8; nt++) {
            const int cb = nt * 8 + 2 * tg;
#pragma unroll
            for (int j = 0; j < 2; j++) {
                float v0 = sacc[nt][j] * SC2;
                float v1 = sacc[nt][2 + j] * SC2;
                if (mb) {
                    if (cb + j > row0 + lim)     v0 = -1e30f;
                    if (cb + j > row0 + 8 + lim) v1 = -1e30f;
                }
                sacc[nt][j] = v0; sacc[nt][2 + j] = v1;
                mx0 = fmaxf(mx0, v0); mx1 = fmaxf(mx1, v1);
            }
        }
        mx0 = fmaxf(mx0, __shfl_xor_sync(0xffffffffu, mx0, 1));
        mx0 = fmaxf(mx0, __shfl_xor_sync(0xffffffffu, mx0, 2));
        mx1 = fmaxf(mx1, __shfl_xor_sync(0xffffffffu, mx1, 1));
        mx1 = fmaxf(mx1, __shfl_xor_sync(0xffffffffu, mx1, 2));

        const float nm0 = fmaxf(m0, mx0), nm1 = fmaxf(m1, mx1);
        const float corr0 = exp2f(m0 - nm0), corr1 = exp2f(m1 - nm1);
        m0 = nm0; m1 = nm1;

        float rs0 = 0.f, rs1 = 0.f;
#pragma unroll
        for (int nt = 0; nt < 8; nt++) {
            float p0 = exp2f(sacc[nt][0] - nm0);
            float p1 = exp2f(sacc[nt][1] - nm0);
            float p2 = exp2f(sacc[nt][2] - nm1);
            float p3 = exp2f(sacc[nt][3] - nm1);
            rs0 += p0 + p1; rs1 += p2 + p3;
            uint32_t hh, ll;
            const int pa = row0 * FSP + nt * 4 + tg;          // pair = (nt*8+2tg)/2
            bfsplit2(p0, p1, hh, ll); Ph[pa] = hh; Pl[pa] = ll;
            const int pb = (row0 + 8) * FSP + nt * 4 + tg;
            bfsplit2(p2, p3, hh, ll); Ph[pb] = hh; Pl[pb] = ll;
        }
        rs0 += __shfl_xor_sync(0xffffffffu, rs0, 1);
        rs0 += __shfl_xor_sync(0xffffffffu, rs0, 2);
        rs1 += __shfl_xor_sync(0xffffffffu, rs1, 1);
        rs1 += __shfl_xor_sync(0xffffffffu, rs1, 2);
        l0 = l0 * corr0 + rs0;
        l1 = l1 * corr1 + rs1;

#pragma unroll
        for (int nt = 0; nt < 8; nt++) {
            oacc[nt][0] *= corr0; oacc[nt][1] *= corr0;
            oacc[nt][2] *= corr1; oacc[nt][3] *= corr1;
        }
        __syncwarp();   // P tile is warp-private (rows 16w..16w+15)

        // --- O += P V, bf16x3 (4 k16 steps over s) ---
#pragma unroll
        for (int ks = 0; ks < 4; ks++) {
            const int p0 = 8 * ks + tg;
            const int ar = row0 * FSP;
            uint32_t ph[4], pl[4];
            ph[0] = Ph[ar + p0];            ph[1] = Ph[ar + 8 * FSP + p0];
            ph[2] = Ph[ar + p0 + 4];        ph[3] = Ph[ar + 8 * FSP + p0 + 4];
            pl[0] = Pl[ar + p0];            pl[1] = Pl[ar + 8 * FSP + p0];
            pl[2] = Pl[ar + p0 + 4];        pl[3] = Pl[ar + 8 * FSP + p0 + 4];
#pragma unroll
            for (int nt = 0; nt < 8; nt++) {
                const int br = (nt * 8 + g) * FSP;
                uint32_t vh[2] = { Vth[br + p0], Vth[br + p0 + 4] };
                uint32_t vl[2] = { Vtl[br + p0], Vtl[br + p0 + 4] };
                mma16(oacc[nt], ph, vh);
                mma16(oacc[nt], ph, vl);
                mma16(oacc[nt], pl, vh);
            }
        }
        __syncwarp();   // done reading warp-private P before next overwrite
    }

    // --- epilogue: normalize, store [T][D] ---
    const float inv0 = 1.0f / l0, inv1 = 1.0f / l1;
#pragma unroll
    for (int nt = 0; nt < 8; nt++) {
        const int cb = hcol + nt * 8 + 2 * tg;
        *(float2*)&out[(size_t)(q0 + row0) * D_DIM + cb] =
            make_float2(oacc[nt][0] * inv0, oacc[nt][1] * inv0);
        *(float2*)&out[(size_t)(q0 + row0 + 8) * D_DIM + cb] =
            make_float2(oacc[nt][2] * inv1, oacc[nt][3] * inv1);
    }
}

// ---------------------------------------------------------------------------
extern "C" void kernel_launch(void* const* d_in, const int* in_sizes, int n_in,
                              void* d_out, int out_size) {
    const float* x     = (const float*)d_in[0];  // [4096,1024]
    const float* Wqkv  = (const float*)d_in[1];  // [3072,1024]
    const float* Wproj = (const float*)d_in[2];  // [1024,1024]
    float* out = (float*)d_out;                  // [4096,1024]

    float* qkv; cudaGetSymbolAddress((void**)&qkv, g_qkv);
    float* att; cudaGetSymbolAddress((void**)&att, g_att);

    cudaFuncSetAttribute(flash_attn_tc, cudaFuncAttributeMaxDynamicSharedMemorySize, FA_SMEM);

    // 1) qkv = x @ W_qkv^T
    dim3 g1((3 * D_DIM) / 128, T_DIM / 128);
    gemm_mma_bf16x3<<<g1, 256>>>(x, Wqkv, qkv, T_DIM, 3 * D_DIM, D_DIM);

    // 2) RoPE in place on q, k
    int total = T_DIM * H_NUM * (C_DIM / 2);
    rope_kernel<<<(total + 255) / 256, 256>>>(qkv);

    // 3) causal flash attention (bf16x3 tensor cores) -> att [T][D]
    dim3 g2(T_DIM / 128, H_NUM);
    flash_attn_tc<<<g2, 256, FA_SMEM>>>(qkv, att);

    // 4) out = att @ W_proj^T
    dim3 g3(D_DIM / 128, T_DIM / 128);
    gemm_mma_bf16x3<<<g3, 256>>>(att, Wproj, out, T_DIM, D_DIM, D_DIM);
}

// round 12
// speedup vs baseline: 1.9434x; 1.0633x over previous
#include <cuda_runtime.h>
#include <cuda_bf16.h>
#include <math.h>
#include <stdint.h>

#define T_DIM 4096
#define D_DIM 1024
#define H_NUM 16
#define C_DIM 64
#define SP   12   // gemm plane row stride (8 bf16-pairs + 4 pad), uint32 units
#define FSP  36   // flash plane row stride (32 bf16-pairs + 4 pad), uint32 units

// Scratch (allocations forbidden -> device globals)
__device__ float g_qkv[T_DIM * 3 * D_DIM];   // [T][3*D]
__device__ float g_att[T_DIM * D_DIM];       // [T][D]

// ---------------------------------------------------------------------------
// helpers
// ---------------------------------------------------------------------------
__device__ __forceinline__ uint32_t bfpack(float a, float b) {
    __nv_bfloat162 t = __floats2bfloat162_rn(a, b);   // low half = a (k-even)
    return *(uint32_t*)&t;
}
// split (a,b) fp32 -> hi pair + lo pair (bf16x3 decomposition)
__device__ __forceinline__ void bfsplit2(float a, float b, uint32_t& hi, uint32_t& lo) {
    float ha = __bfloat162float(__float2bfloat16_rn(a));
    float hb = __bfloat162float(__float2bfloat16_rn(b));
    hi = bfpack(ha, hb);
    lo = bfpack(a - ha, b - hb);
}
__device__ __forceinline__ void mma16(float* d, const uint32_t* a, const uint32_t* b) {
    asm volatile(
        "mma.sync.aligned.m16n8k16.row.col.f32.bf16.bf16.f32 "
        "{%0,%1,%2,%3}, {%4,%5,%6,%7}, {%8,%9}, {%0,%1,%2,%3};"
        : "+f"(d[0]), "+f"(d[1]), "+f"(d[2]), "+f"(d[3])
        : "r"(a[0]), "r"(a[1]), "r"(a[2]), "r"(a[3]), "r"(b[0]), "r"(b[1]));
}

// ===========================================================================
// mma.sync bf16x3 GEMM: C[M,N] = A[M,K] * B[N,K]^T (fp32 io)
// 128x128 CTA tile, K-chunk 16, 256 threads, 8 warps 64x32.
// __launch_bounds__(256,2): cap regs at 128 -> 2 CTAs/SM (was 153 regs, occ 1).
// ===========================================================================
__global__ void __launch_bounds__(256, 2) gemm_mma_bf16x3(
    const float* __restrict__ A, const float* __restrict__ B, float* __restrict__ C,
    int M, int N, int K)
{
    __shared__ uint32_t sAh[128 * SP];
    __shared__ uint32_t sAl[128 * SP];
    __shared__ uint32_t sBh[128 * SP];
    __shared__ uint32_t sBl[128 * SP];

    const int tid  = threadIdx.x;
    const int lane = tid & 31;
    const int g    = lane >> 2;    // group id
    const int tg   = lane & 3;     // thread in group
    const int wid  = tid >> 5;
    const int wm   = wid >> 2;
    const int wn   = wid & 3;
    const int bm   = blockIdx.y * 128;
    const int bn   = blockIdx.x * 128;

    // loader: 4 threads per row, 4 floats each (chunk = 16 floats/row)
    const int r0g = (tid + 0)   >> 2, c0g = ((tid + 0)   & 3) * 4;
    const int r1g = (tid + 256) >> 2, c1g = ((tid + 256) & 3) * 4;
    const float* A0 = A + (size_t)(bm + r0g) * K + c0g;
    const float* A1 = A + (size_t)(bm + r1g) * K + c1g;
    const float* B0 = B + (size_t)(bn + r0g) * K + c0g;
    const float* B1 = B + (size_t)(bn + r1g) * K + c1g;
    const int sa0 = r0g * SP + (c0g >> 1), sa1 = r1g * SP + (c1g >> 1);

    float acc[4][4][4];
#pragma unroll
    for (int i = 0; i < 4; i++)
#pragma unroll
        for (int j = 0; j < 4; j++)
#pragma unroll
            for (int k = 0; k < 4; k++) acc[i][j][k] = 0.f;

    const int nch = K >> 4;
    float4 ra0 = *(const float4*)A0, ra1 = *(const float4*)A1;
    float4 rb0 = *(const float4*)B0, rb1 = *(const float4*)B1;

    for (int c = 0; c < nch; c++) {
        {
            uint32_t h, l;
            bfsplit2(ra0.x, ra0.y, h, l); sAh[sa0]     = h; sAl[sa0]     = l;
            bfsplit2(ra0.z, ra0.w, h, l); sAh[sa0 + 1] = h; sAl[sa0 + 1] = l;
            bfsplit2(ra1.x, ra1.y, h, l); sAh[sa1]     = h; sAl[sa1]     = l;
            bfsplit2(ra1.z, ra1.w, h, l); sAh[sa1 + 1] = h; sAl[sa1 + 1] = l;
            bfsplit2(rb0.x, rb0.y, h, l); sBh[sa0]     = h; sBl[sa0]     = l;
            bfsplit2(rb0.z, rb0.w, h, l); sBh[sa0 + 1] = h; sBl[sa0 + 1] = l;
            bfsplit2(rb1.x, rb1.y, h, l); sBh[sa1]     = h; sBl[sa1]     = l;
            bfsplit2(rb1.z, rb1.w, h, l); sBh[sa1 + 1] = h; sBl[sa1 + 1] = l;
        }
        __syncthreads();

        if (c + 1 < nch) {
            const int off = (c + 1) * 16;
            ra0 = *(const float4*)(A0 + off); ra1 = *(const float4*)(A1 + off);
            rb0 = *(const float4*)(B0 + off); rb1 = *(const float4*)(B1 + off);
        }

        // one m16n8k16 step per chunk
        {
            uint32_t ah[4][4], al[4][4], bh[4][2], bl[4][2];
#pragma unroll
            for (int mt = 0; mt < 4; mt++) {
                const int r = (wm * 64 + mt * 16 + g) * SP;
                ah[mt][0] = sAh[r + tg];           ah[mt][1] = sAh[r + 8 * SP + tg];
                ah[mt][2] = sAh[r + tg + 4];       ah[mt][3] = sAh[r + 8 * SP + tg + 4];
                al[mt][0] = sAl[r + tg];           al[mt][1] = sAl[r + 8 * SP + tg];
                al[mt][2] = sAl[r + tg + 4];       al[mt][3] = sAl[r + 8 * SP + tg + 4];
            }
#pragma unroll
            for (int nt = 0; nt < 4; nt++) {
                const int r = (wn * 32 + nt * 8 + g) * SP;
                bh[nt][0] = sBh[r + tg];  bh[nt][1] = sBh[r + tg + 4];
                bl[nt][0] = sBl[r + tg];  bl[nt][1] = sBl[r + tg + 4];
            }
#pragma unroll
            for (int mt = 0; mt < 4; mt++)
#pragma unroll
                for (int nt = 0; nt < 4; nt++) {
                    mma16(acc[mt][nt], ah[mt], bh[nt]);
                    mma16(acc[mt][nt], ah[mt], bl[nt]);
                    mma16(acc[mt][nt], al[mt], bh[nt]);
                }
        }
        __syncthreads();
    }

#pragma unroll
    for (int mt = 0; mt < 4; mt++) {
        const int row = bm + wm * 64 + mt * 16 + g;
#pragma unroll
        for (int nt = 0; nt < 4; nt++) {
            const int col = bn + wn * 32 + nt * 8 + 2 * tg;
            *(float2*)&C[(size_t)row * N + col] =
                make_float2(acc[mt][nt][0], acc[mt][nt][1]);
            *(float2*)&C[(size_t)(row + 8) * N + col] =
                make_float2(acc[mt][nt][2], acc[mt][nt][3]);
        }
    }
}

// ---------------------------------------------------------------------------
// RoPE in place on q,k inside g_qkv [T][3*D]
// ---------------------------------------------------------------------------
__global__ void rope_kernel(float* __restrict__ qkv) {
    int idx = blockIdx.x * blockDim.x + threadIdx.x;
    if (idx >= T_DIM * H_NUM * (C_DIM / 2)) return;
    int t = idx >> 9;
    int r = idx & 511;
    int h = r >> 5;
    int p = r & 31;

    float inv_freq = expf(-(float)p * (logf(10000.0f) / 32.0f));
    float ang = (float)t * inv_freq;
    float s, c;
    sincosf(ang, &s, &c);

    size_t base_q = (size_t)t * (3 * D_DIM) + h * C_DIM + 2 * p;
    size_t base_k = base_q + D_DIM;

    float x1 = qkv[base_q], x2 = qkv[base_q + 1];
    qkv[base_q]     = x1 * c - x2 * s;
    qkv[base_q + 1] = x2 * c + x1 * s;

    float y1 = qkv[base_k], y2 = qkv[base_k + 1];
    qkv[base_k]     = y1 * c - y2 * s;
    qkv[base_k + 1] = y2 * c + y1 * s;
}

// ===========================================================================
// Tensor-core flash attention, bf16x3 (m16n8k16), causal.
// Bq=128, Bk=64, C=64, 256 threads / 8 warps.
// __launch_bounds__(256,2) + no register prefetch (proven worthless in R8;
// frees 32 regs) -> 2 CTAs/SM (2 x 110,592 B smem = 221 KB <= 228 KB/SM);
// cross-CTA overlap hides gmem latency.
// ===========================================================================
#define FA_SMEM ((2 * 128 + 2 * 64 + 2 * 64 + 2 * 128) * FSP * 4)
#define SC2 0.18033688f   // 0.125 * log2(e)

__global__ void __launch_bounds__(256, 2) flash_attn_tc(
    const float* __restrict__ qkv, float* __restrict__ out)
{
    extern __shared__ uint32_t smu[];
    uint32_t* Qh  = smu;
    uint32_t* Ql  = Qh  + 128 * FSP;
    uint32_t* Kh  = Ql  + 128 * FSP;
    uint32_t* Kl  = Kh  + 64 * FSP;
    uint32_t* Vth = Kl  + 64 * FSP;   // V^T: row=c, pairs over s
    uint32_t* Vtl = Vth + 64 * FSP;
    uint32_t* Ph  = Vtl + 64 * FSP;
    uint32_t* Pl  = Ph  + 128 * FSP;

    const int h    = blockIdx.y;
    const int qb   = gridDim.x - 1 - blockIdx.x;   // big blocks first
    const int q0   = qb * 128;
    const int tid  = threadIdx.x;
    const int lane = tid & 31;
    const int g    = lane >> 2;
    const int tg   = lane & 3;
    const int wid  = tid >> 5;
    const int hcol = h * C_DIM;
    const int row0 = wid * 16 + g;                 // local S/O row of c0,c1

    // loader mappings
    const int kr   = tid >> 4;          // K/Q row base (idx=tid+256i -> row kr+16i)
    const int kc4  = (tid & 15) * 4;    // K/Q col group (4 floats = 2 pairs)
    const int vc   = tid & 63;          // V column (head dim c) -> V^T row
    const int vr4  = (tid >> 6) * 4;    // V s-chunk base

    // --- load Q tile [128][64], split to bf16 hi/lo pair planes ---
#pragma unroll
    for (int i = 0; i < 8; i++) {
        int idx = tid + 256 * i;
        int r = idx >> 4, c4 = (idx & 15) * 4;
        float4 v = *(const float4*)&qkv[(size_t)(q0 + r) * (3 * D_DIM) + hcol + c4];
        uint32_t hh, ll;
        int sa = r * FSP + (c4 >> 1);
        bfsplit2(v.x, v.y, hh, ll); Qh[sa]     = hh; Ql[sa]     = ll;
        bfsplit2(v.z, v.w, hh, ll); Qh[sa + 1] = hh; Ql[sa + 1] = ll;
    }

    float m0 = -1e30f, m1 = -1e30f, l0 = 0.f, l1 = 0.f;
    float oacc[8][4];
#pragma unroll
    for (int nt = 0; nt < 8; nt++)
#pragma unroll
        for (int j = 0; j < 4; j++) oacc[nt][j] = 0.f;

    const float* kbase = qkv + 1024 + hcol + (size_t)kr * (3 * D_DIM) + kc4;
    const float* vbase = qkv + 2048 + hcol + vc;

    const int kbmax = 2 * qb + 1;
    for (int kb = 0; kb <= kbmax; kb++) {
        __syncthreads();  // all warps done reading prior K/V smem

        // --- load K/V tile from gmem, split to smem planes ---
        {
            const size_t off = (size_t)kb * 64 * (3 * D_DIM);
#pragma unroll
            for (int i = 0; i < 4; i++) {
                const int r = kr + 16 * i;
                float4 kv = *(const float4*)(kbase + off + (size_t)(16 * i) * (3 * D_DIM));
                uint32_t hh, ll;
                int ka = r * FSP + (kc4 >> 1);
                bfsplit2(kv.x, kv.y, hh, ll); Kh[ka]     = hh; Kl[ka]     = ll;
                bfsplit2(kv.z, kv.w, hh, ll); Kh[ka + 1] = hh; Kl[ka + 1] = ll;

                float v0 = vbase[off + (size_t)(vr4 + 16 * i + 0) * (3 * D_DIM)];
                float v1 = vbase[off + (size_t)(vr4 + 16 * i + 1) * (3 * D_DIM)];
                float v2 = vbase[off + (size_t)(vr4 + 16 * i + 2) * (3 * D_DIM)];
                float v3 = vbase[off + (size_t)(vr4 + 16 * i + 3) * (3 * D_DIM)];
                int va = vc * FSP + ((vr4 + 16 * i) >> 1);
                bfsplit2(v0, v1, hh, ll); Vth[va]     = hh; Vtl[va]     = ll;
                bfsplit2(v2, v3, hh, ll); Vth[va + 1] = hh; Vtl[va + 1] = ll;
            }
        }
        __syncthreads();

        // --- S = Q K^T, bf16x3 (4 k16 steps) ---
        float sacc[8][4];
#pragma unroll
        for (int nt = 0; nt < 8; nt++)
#pragma unroll
            for (int j = 0; j < 4; j++) sacc[nt][j] = 0.f;

#pragma unroll
        for (int ks = 0; ks < 4; ks++) {
            const int p0 = 8 * ks + tg;           // pair index of a0/b0
            const int ar = row0 * FSP;
            uint32_t ah[4], al[4];
            ah[0] = Qh[ar + p0];            ah[1] = Qh[ar + 8 * FSP + p0];
            ah[2] = Qh[ar + p0 + 4];        ah[3] = Qh[ar + 8 * FSP + p0 + 4];
            al[0] = Ql[ar + p0];            al[1] = Ql[ar + 8 * FSP + p0];
            al[2] = Ql[ar + p0 + 4];        al[3] = Ql[ar + 8 * FSP + p0 + 4];
#pragma unroll
            for (int nt = 0; nt < 8; nt++) {
                const int br = (nt * 8 + g) * FSP;
                uint32_t bh[2] = { Kh[br + p0], Kh[br + p0 + 4] };
                uint32_t bl[2] = { Kl[br + p0], Kl[br + p0 + 4] };
                mma16(sacc[nt], ah, bh);
                mma16(sacc[nt], ah, bl);
                mma16(sacc[nt], al, bh);
            }
        }

        // --- scale (log2 domain) + causal mask ---
        const bool mb = (kb >= 2 * qb);
        const int lim = q0 - kb * 64;   // keep col c if c <= row + lim
        float mx0 = -1e30f, mx1 = -1e30f;
#pragma unroll
        for (int nt = 0; nt < 8; nt++) {
            const int cb = nt * 8 + 2 * tg;
#pragma unroll
            for (int j = 0; j < 2; j++) {
                float v0 = sacc[nt][j] * SC2;
                float v1 = sacc[nt][2 + j] * SC2;
                if (mb) {
                    if (cb + j > row0 + lim)     v0 = -1e30f;
                    if (cb + j > row0 + 8 + lim) v1 = -1e30f;
                }
                sacc[nt][j] = v0; sacc[nt][2 + j] = v1;
                mx0 = fmaxf(mx0, v0); mx1 = fmaxf(mx1, v1);
            }
        }
        mx0 = fmaxf(mx0, __shfl_xor_sync(0xffffffffu, mx0, 1));
        mx0 = fmaxf(mx0, __shfl_xor_sync(0xffffffffu, mx0, 2));
        mx1 = fmaxf(mx1, __shfl_xor_sync(0xffffffffu, mx1, 1));
        mx1 = fmaxf(mx1, __shfl_xor_sync(0xffffffffu, mx1, 2));

        const float nm0 = fmaxf(m0, mx0), nm1 = fmaxf(m1, mx1);
        const float corr0 = exp2f(m0 - nm0), corr1 = exp2f(m1 - nm1);
        m0 = nm0; m1 = nm1;

        float rs0 = 0.f, rs1 = 0.f;
#pragma unroll
        for (int nt = 0; nt < 8; nt++) {
            float p0 = exp2f(sacc[nt][0] - nm0);
            float p1 = exp2f(sacc[nt][1] - nm0);
            float p2 = exp2f(sacc[nt][2] - nm1);
            float p3 = exp2f(sacc[nt][3] - nm1);
            rs0 += p0 + p1; rs1 += p2 + p3;
            uint32_t hh, ll;
            const int pa = row0 * FSP + nt * 4 + tg;          // pair = (nt*8+2tg)/2
            bfsplit2(p0, p1, hh, ll); Ph[pa] = hh; Pl[pa] = ll;
            const int pb = (row0 + 8) * FSP + nt * 4 + tg;
            bfsplit2(p2, p3, hh, ll); Ph[pb] = hh; Pl[pb] = ll;
        }
        rs0 += __shfl_xor_sync(0xffffffffu, rs0, 1);
        rs0 += __shfl_xor_sync(0xffffffffu, rs0, 2);
        rs1 += __shfl_xor_sync(0xffffffffu, rs1, 1);
        rs1 += __shfl_xor_sync(0xffffffffu, rs1, 2);
        l0 = l0 * corr0 + rs0;
        l1 = l1 * corr1 + rs1;

#pragma unroll
        for (int nt = 0; nt < 8; nt++) {
            oacc[nt][0] *= corr0; oacc[nt][1] *= corr0;
            oacc[nt][2] *= corr1; oacc[nt][3] *= corr1;
        }
        __syncwarp();   // P tile is warp-private (rows 16w..16w+15)

        // --- O += P V, bf16x3 (4 k16 steps over s) ---
#pragma unroll
        for (int ks = 0; ks < 4; ks++) {
            const int p0 = 8 * ks + tg;
            const int ar = row0 * FSP;
            uint32_t ph[4], pl[4];
            ph[0] = Ph[ar + p0];            ph[1] = Ph[ar + 8 * FSP + p0];
            ph[2] = Ph[ar + p0 + 4];        ph[3] = Ph[ar + 8 * FSP + p0 + 4];
            pl[0] = Pl[ar + p0];            pl[1] = Pl[ar + 8 * FSP + p0];
            pl[2] = Pl[ar + p0 + 4];        pl[3] = Pl[ar + 8 * FSP + p0 + 4];
#pragma unroll
            for (int nt = 0; nt < 8; nt++) {
                const int br = (nt * 8 + g) * FSP;
                uint32_t vh[2] = { Vth[br + p0], Vth[br + p0 + 4] };
                uint32_t vl[2] = { Vtl[br + p0], Vtl[br + p0 + 4] };
                mma16(oacc[nt], ph, vh);
                mma16(oacc[nt], ph, vl);
                mma16(oacc[nt], pl, vh);
            }
        }
        __syncwarp();   // done reading warp-private P before next overwrite
    }

    // --- epilogue: normalize, store [T][D] ---
    const float inv0 = 1.0f / l0, inv1 = 1.0f / l1;
#pragma unroll
    for (int nt = 0; nt < 8; nt++) {
        const int cb = hcol + nt * 8 + 2 * tg;
        *(float2*)&out[(size_t)(q0 + row0) * D_DIM + cb] =
            make_float2(oacc[nt][0] * inv0, oacc[nt][1] * inv0);
        *(float2*)&out[(size_t)(q0 + row0 + 8) * D_DIM + cb] =
            make_float2(oacc[nt][2] * inv1, oacc[nt][3] * inv1);
    }
}

// ---------------------------------------------------------------------------
extern "C" void kernel_launch(void* const* d_in, const int* in_sizes, int n_in,
                              void* d_out, int out_size) {
    const float* x     = (const float*)d_in[0];  // [4096,1024]
    const float* Wqkv  = (const float*)d_in[1];  // [3072,1024]
    const float* Wproj = (const float*)d_in[2];  // [1024,1024]
    float* out = (float*)d_out;                  // [4096,1024]

    float* qkv; cudaGetSymbolAddress((void**)&qkv, g_qkv);
    float* att; cudaGetSymbolAddress((void**)&att, g_att);

    cudaFuncSetAttribute(flash_attn_tc, cudaFuncAttributeMaxDynamicSharedMemorySize, FA_SMEM);

    // 1) qkv = x @ W_qkv^T
    dim3 g1((3 * D_DIM) / 128, T_DIM / 128);
    gemm_mma_bf16x3<<<g1, 256>>>(x, Wqkv, qkv, T_DIM, 3 * D_DIM, D_DIM);

    // 2) RoPE in place on q, k
    int total = T_DIM * H_NUM * (C_DIM / 2);
    rope_kernel<<<(total + 255) / 256, 256>>>(qkv);

    // 3) causal flash attention (bf16x3 tensor cores) -> att [T][D]
    dim3 g2(T_DIM / 128, H_NUM);
    flash_attn_tc<<<g2, 256, FA_SMEM>>>(qkv, att);

    // 4) out = att @ W_proj^T
    dim3 g3(D_DIM / 128, T_DIM / 128);
    gemm_mma_bf16x3<<<g3, 256>>>(att, Wproj, out, T_DIM, D_DIM, D_DIM);
}

// round 13
// speedup vs baseline: 1.9599x; 1.0085x over previous
#include <cuda_runtime.h>
#include <cuda_bf16.h>
#include <math.h>
#include <stdint.h>

#define T_DIM 4096
#define D_DIM 1024
#define H_NUM 16
#define C_DIM 64
#define SP   12   // gemm plane row stride (8 bf16-pairs + 4 pad), uint32 units
#define FSP  36   // flash plane row stride (32 bf16-pairs + 4 pad), uint32 units

// Scratch (allocations forbidden -> device globals)
__device__ float g_qkv[T_DIM * 3 * D_DIM];   // [T][3*D]
__device__ float g_att[T_DIM * D_DIM];       // [T][D]

// ---------------------------------------------------------------------------
// helpers
// ---------------------------------------------------------------------------
__device__ __forceinline__ uint32_t bfpack(float a, float b) {
    __nv_bfloat162 t = __floats2bfloat162_rn(a, b);   // low half = a (k-even)
    return *(uint32_t*)&t;
}
// split (a,b) fp32 -> hi pair + lo pair (bf16x3 decomposition)
__device__ __forceinline__ void bfsplit2(float a, float b, uint32_t& hi, uint32_t& lo) {
    float ha = __bfloat162float(__float2bfloat16_rn(a));
    float hb = __bfloat162float(__float2bfloat16_rn(b));
    hi = bfpack(ha, hb);
    lo = bfpack(a - ha, b - hb);
}
__device__ __forceinline__ void mma16(float* d, const uint32_t* a, const uint32_t* b) {
    asm volatile(
        "mma.sync.aligned.m16n8k16.row.col.f32.bf16.bf16.f32 "
        "{%0,%1,%2,%3}, {%4,%5,%6,%7}, {%8,%9}, {%0,%1,%2,%3};"
        : "+f"(d[0]), "+f"(d[1]), "+f"(d[2]), "+f"(d[3])
        : "r"(a[0]), "r"(a[1]), "r"(a[2]), "r"(a[3]), "r"(b[0]), "r"(b[1]));
}

// ===========================================================================
// mma.sync bf16x3 GEMM, double-buffered: C[M,N] = A[M,K] * B[N,K]^T (fp32 io)
// 128x128 CTA tile, K-chunk 16, 256 threads, 8 warps 64x32, 2 CTAs/SM.
// 2 smem stages; ONE __syncthreads per chunk; STS of chunk c+1 overlaps
// mma of chunk c; gmem loads run 2 chunks ahead.
// ===========================================================================
__global__ void __launch_bounds__(256, 2) gemm_mma_bf16x3(
    const float* __restrict__ A, const float* __restrict__ B, float* __restrict__ C,
    int M, int N, int K)
{
    __shared__ uint32_t sAh[2][128 * SP];
    __shared__ uint32_t sAl[2][128 * SP];
    __shared__ uint32_t sBh[2][128 * SP];
    __shared__ uint32_t sBl[2][128 * SP];

    const int tid  = threadIdx.x;
    const int lane = tid & 31;
    const int g    = lane >> 2;    // group id
    const int tg   = lane & 3;     // thread in group
    const int wid  = tid >> 5;
    const int wm   = wid >> 2;
    const int wn   = wid & 3;
    const int bm   = blockIdx.y * 128;
    const int bn   = blockIdx.x * 128;

    // loader: 4 threads per row, 4 floats each (chunk = 16 floats/row)
    const int r0g = (tid + 0)   >> 2, c0g = ((tid + 0)   & 3) * 4;
    const int r1g = (tid + 256) >> 2, c1g = ((tid + 256) & 3) * 4;
    const float* A0 = A + (size_t)(bm + r0g) * K + c0g;
    const float* A1 = A + (size_t)(bm + r1g) * K + c1g;
    const float* B0 = B + (size_t)(bn + r0g) * K + c0g;
    const float* B1 = B + (size_t)(bn + r1g) * K + c1g;
    const int sa0 = r0g * SP + (c0g >> 1), sa1 = r1g * SP + (c1g >> 1);

    float acc[4][4][4];
#pragma unroll
    for (int i = 0; i < 4; i++)
#pragma unroll
        for (int j = 0; j < 4; j++)
#pragma unroll
            for (int k = 0; k < 4; k++) acc[i][j][k] = 0.f;

    const int nch = K >> 4;

    // store chunk c (held in regs) into stage st
    auto store_stage = [&](int st, const float4& ra0, const float4& ra1,
                           const float4& rb0, const float4& rb1) {
        uint32_t h, l;
        bfsplit2(ra0.x, ra0.y, h, l); sAh[st][sa0]     = h; sAl[st][sa0]     = l;
        bfsplit2(ra0.z, ra0.w, h, l); sAh[st][sa0 + 1] = h; sAl[st][sa0 + 1] = l;
        bfsplit2(ra1.x, ra1.y, h, l); sAh[st][sa1]     = h; sAl[st][sa1]     = l;
        bfsplit2(ra1.z, ra1.w, h, l); sAh[st][sa1 + 1] = h; sAl[st][sa1 + 1] = l;
        bfsplit2(rb0.x, rb0.y, h, l); sBh[st][sa0]     = h; sBl[st][sa0]     = l;
        bfsplit2(rb0.z, rb0.w, h, l); sBh[st][sa0 + 1] = h; sBl[st][sa0 + 1] = l;
        bfsplit2(rb1.x, rb1.y, h, l); sBh[st][sa1]     = h; sBl[st][sa1]     = l;
        bfsplit2(rb1.z, rb1.w, h, l); sBh[st][sa1 + 1] = h; sBl[st][sa1 + 1] = l;
    };

    float4 ra0 = *(const float4*)A0, ra1 = *(const float4*)A1;
    float4 rb0 = *(const float4*)B0, rb1 = *(const float4*)B1;
    store_stage(0, ra0, ra1, rb0, rb1);
    if (nch > 1) {
        ra0 = *(const float4*)(A0 + 16); ra1 = *(const float4*)(A1 + 16);
        rb0 = *(const float4*)(B0 + 16); rb1 = *(const float4*)(B1 + 16);
    }
    __syncthreads();

    for (int c = 0; c < nch; c++) {
        const int b = c & 1;

        // store chunk c+1 to other stage (overlaps compute below), then
        // prefetch chunk c+2 into regs
        if (c + 1 < nch) {
            store_stage(1 - b, ra0, ra1, rb0, rb1);
            if (c + 2 < nch) {
                const int off = (c + 2) * 16;
                ra0 = *(const float4*)(A0 + off); ra1 = *(const float4*)(A1 + off);
                rb0 = *(const float4*)(B0 + off); rb1 = *(const float4*)(B1 + off);
            }
        }

        // compute chunk c from stage b
        {
            uint32_t ah[4][4], al[4][4], bh[4][2], bl[4][2];
#pragma unroll
            for (int mt = 0; mt < 4; mt++) {
                const int r = (wm * 64 + mt * 16 + g) * SP;
                ah[mt][0] = sAh[b][r + tg];           ah[mt][1] = sAh[b][r + 8 * SP + tg];
                ah[mt][2] = sAh[b][r + tg + 4];       ah[mt][3] = sAh[b][r + 8 * SP + tg + 4];
                al[mt][0] = sAl[b][r + tg];           al[mt][1] = sAl[b][r + 8 * SP + tg];
                al[mt][2] = sAl[b][r + tg + 4];       al[mt][3] = sAl[b][r + 8 * SP + tg + 4];
            }
#pragma unroll
            for (int nt = 0; nt < 4; nt++) {
                const int r = (wn * 32 + nt * 8 + g) * SP;
                bh[nt][0] = sBh[b][r + tg];  bh[nt][1] = sBh[b][r + tg + 4];
                bl[nt][0] = sBl[b][r + tg];  bl[nt][1] = sBl[b][r + tg + 4];
            }
#pragma unroll
            for (int mt = 0; mt < 4; mt++)
#pragma unroll
                for (int nt = 0; nt < 4; nt++) {
                    mma16(acc[mt][nt], ah[mt], bh[nt]);
                    mma16(acc[mt][nt], ah[mt], bl[nt]);
                    mma16(acc[mt][nt], al[mt], bh[nt]);
                }
        }
        __syncthreads();   // stage b free for writes; stage 1-b stores complete
    }

#pragma unroll
    for (int mt = 0; mt < 4; mt++) {
        const int row = bm + wm * 64 + mt * 16 + g;
#pragma unroll
        for (int nt = 0; nt < 4; nt++) {
            const int col = bn + wn * 32 + nt * 8 + 2 * tg;
            *(float2*)&C[(size_t)row * N + col] =
                make_float2(acc[mt][nt][0], acc[mt][nt][1]);
            *(float2*)&C[(size_t)(row + 8) * N + col] =
                make_float2(acc[mt][nt][2], acc[mt][nt][3]);
        }
    }
}

// ---------------------------------------------------------------------------
// RoPE in place on q,k inside g_qkv [T][3*D]
// ---------------------------------------------------------------------------
__global__ void rope_kernel(float* __restrict__ qkv) {
    int idx = blockIdx.x * blockDim.x + threadIdx.x;
    if (idx >= T_DIM * H_NUM * (C_DIM / 2)) return;
    int t = idx >> 9;
    int r = idx & 511;
    int h = r >> 5;
    int p = r & 31;

    float inv_freq = expf(-(float)p * (logf(10000.0f) / 32.0f));
    float ang = (float)t * inv_freq;
    float s, c;
    sincosf(ang, &s, &c);

    size_t base_q = (size_t)t * (3 * D_DIM) + h * C_DIM + 2 * p;
    size_t base_k = base_q + D_DIM;

    float x1 = qkv[base_q], x2 = qkv[base_q + 1];
    qkv[base_q]     = x1 * c - x2 * s;
    qkv[base_q + 1] = x2 * c + x1 * s;

    float y1 = qkv[base_k], y2 = qkv[base_k + 1];
    qkv[base_k]     = y1 * c - y2 * s;
    qkv[base_k + 1] = y2 * c + y1 * s;
}

// ===========================================================================
// Tensor-core flash attention, bf16x3 (m16n8k16), causal.
// Bq=128, Bk=64, C=64, 256 threads / 8 warps, 2 CTAs/SM.
// P NEVER touches smem: the m16n8k16 accumulator layout (rows g,g+8 x cols
// 2tg,2tg+1) IS the A-fragment layout over s, so softmax outputs pack
// directly into PV A-fragments (phi/plo). Smem: Q,K,V planes only = 73,728 B.
// ===========================================================================
#define FA_SMEM ((2 * 128 + 2 * 64 + 2 * 64) * FSP * 4)
#define SC2 0.18033688f   // 0.125 * log2(e)

__global__ void __launch_bounds__(256, 2) flash_attn_tc(
    const float* __restrict__ qkv, float* __restrict__ out)
{
    extern __shared__ uint32_t smu[];
    uint32_t* Qh  = smu;
    uint32_t* Ql  = Qh  + 128 * FSP;
    uint32_t* Kh  = Ql  + 128 * FSP;
    uint32_t* Kl  = Kh  + 64 * FSP;
    uint32_t* Vth = Kl  + 64 * FSP;   // V^T: row=c, pairs over s
    uint32_t* Vtl = Vth + 64 * FSP;

    const int h    = blockIdx.y;
    const int qb   = gridDim.x - 1 - blockIdx.x;   // big blocks first
    const int q0   = qb * 128;
    const int tid  = threadIdx.x;
    const int lane = tid & 31;
    const int g    = lane >> 2;
    const int tg   = lane & 3;
    const int wid  = tid >> 5;
    const int hcol = h * C_DIM;
    const int row0 = wid * 16 + g;                 // local S/O row of c0,c1

    // loader mappings
    const int kr   = tid >> 4;          // K/Q row base (idx=tid+256i -> row kr+16i)
    const int kc4  = (tid & 15) * 4;    // K/Q col group (4 floats = 2 pairs)
    const int vc   = tid & 63;          // V column (head dim c) -> V^T row
    const int vr4  = (tid >> 6) * 4;    // V s-chunk base

    // --- load Q tile [128][64], split to bf16 hi/lo pair planes ---
#pragma unroll
    for (int i = 0; i < 8; i++) {
        int idx = tid + 256 * i;
        int r = idx >> 4, c4 = (idx & 15) * 4;
        float4 v = *(const float4*)&qkv[(size_t)(q0 + r) * (3 * D_DIM) + hcol + c4];
        uint32_t hh, ll;
        int sa = r * FSP + (c4 >> 1);
        bfsplit2(v.x, v.y, hh, ll); Qh[sa]     = hh; Ql[sa]     = ll;
        bfsplit2(v.z, v.w, hh, ll); Qh[sa + 1] = hh; Ql[sa + 1] = ll;
    }

    float m0 = -1e30f, m1 = -1e30f, l0 = 0.f, l1 = 0.f;
    float oacc[8][4];
#pragma unroll
    for (int nt = 0; nt < 8; nt++)
#pragma unroll
        for (int j = 0; j < 4; j++) oacc[nt][j] = 0.f;

    const float* kbase = qkv + 1024 + hcol + (size_t)kr * (3 * D_DIM) + kc4;
    const float* vbase = qkv + 2048 + hcol + vc;

    const int kbmax = 2 * qb + 1;
    for (int kb = 0; kb <= kbmax; kb++) {
        __syncthreads();  // all warps done reading prior K/V smem

        // --- load K/V tile from gmem, split to smem planes ---
        {
            const size_t off = (size_t)kb * 64 * (3 * D_DIM);
#pragma unroll
            for (int i = 0; i < 4; i++) {
                const int r = kr + 16 * i;
                float4 kv = *(const float4*)(kbase + off + (size_t)(16 * i) * (3 * D_DIM));
                uint32_t hh, ll;
                int ka = r * FSP + (kc4 >> 1);
                bfsplit2(kv.x, kv.y, hh, ll); Kh[ka]     = hh; Kl[ka]     = ll;
                bfsplit2(kv.z, kv.w, hh, ll); Kh[ka + 1] = hh; Kl[ka + 1] = ll;

                float v0 = vbase[off + (size_t)(vr4 + 16 * i + 0) * (3 * D_DIM)];
                float v1 = vbase[off + (size_t)(vr4 + 16 * i + 1) * (3 * D_DIM)];
                float v2 = vbase[off + (size_t)(vr4 + 16 * i + 2) * (3 * D_DIM)];
                float v3 = vbase[off + (size_t)(vr4 + 16 * i + 3) * (3 * D_DIM)];
                int va = vc * FSP + ((vr4 + 16 * i) >> 1);
                bfsplit2(v0, v1, hh, ll); Vth[va]     = hh; Vtl[va]     = ll;
                bfsplit2(v2, v3, hh, ll); Vth[va + 1] = hh; Vtl[va + 1] = ll;
            }
        }
        __syncthreads();

        // --- S = Q K^T, bf16x3 (4 k16 steps) ---
        float sacc[8][4];
#pragma unroll
        for (int nt = 0; nt < 8; nt++)
#pragma unroll
            for (int j = 0; j < 4; j++) sacc[nt][j] = 0.f;

#pragma unroll
        for (int ks = 0; ks < 4; ks++) {
            const int p0 = 8 * ks + tg;           // pair index of a0/b0
            const int ar = row0 * FSP;
            uint32_t ah[4], al[4];
            ah[0] = Qh[ar + p0];            ah[1] = Qh[ar + 8 * FSP + p0];
            ah[2] = Qh[ar + p0 + 4];        ah[3] = Qh[ar + 8 * FSP + p0 + 4];
            al[0] = Ql[ar + p0];            al[1] = Ql[ar + 8 * FSP + p0];
            al[2] = Ql[ar + p0 + 4];        al[3] = Ql[ar + 8 * FSP + p0 + 4];
#pragma unroll
            for (int nt = 0; nt < 8; nt++) {
                const int br = (nt * 8 + g) * FSP;
                uint32_t bh[2] = { Kh[br + p0], Kh[br + p0 + 4] };
                uint32_t bl[2] = { Kl[br + p0], Kl[br + p0 + 4] };
                mma16(sacc[nt], ah, bh);
                mma16(sacc[nt], ah, bl);
                mma16(sacc[nt], al, bh);
            }
        }

        // --- scale (log2 domain) + causal mask ---
        const bool mb = (kb >= 2 * qb);
        const int lim = q0 - kb * 64;   // keep col c if c <= row + lim
        float mx0 = -1e30f, mx1 = -1e30f;
#pragma unroll
        for (int nt = 0; nt < 8; nt++) {
            const int cb = nt * 8 + 2 * tg;
#pragma unroll
            for (int j = 0; j < 2; j++) {
                float v0 = sacc[nt][j] * SC2;
                float v1 = sacc[nt][2 + j] * SC2;
                if (mb) {
                    if (cb + j > row0 + lim)     v0 = -1e30f;
                    if (cb + j > row0 + 8 + lim) v1 = -1e30f;
                }
                sacc[nt][j] = v0; sacc[nt][2 + j] = v1;
                mx0 = fmaxf(mx0, v0); mx1 = fmaxf(mx1, v1);
            }
        }
        mx0 = fmaxf(mx0, __shfl_xor_sync(0xffffffffu, mx0, 1));
        mx0 = fmaxf(mx0, __shfl_xor_sync(0xffffffffu, mx0, 2));
        mx1 = fmaxf(mx1, __shfl_xor_sync(0xffffffffu, mx1, 1));
        mx1 = fmaxf(mx1, __shfl_xor_sync(0xffffffffu, mx1, 2));

        const float nm0 = fmaxf(m0, mx0), nm1 = fmaxf(m1, mx1);
        const float corr0 = exp2f(m0 - nm0), corr1 = exp2f(m1 - nm1);
        m0 = nm0; m1 = nm1;

        // --- softmax -> P packed DIRECTLY into PV A-fragments (no smem) ---
        // phi[ks] covers s-cols 16ks..16ks+15: regs = {nt=2ks (rows r0,r0+8),
        // nt=2ks+1 (rows r0,r0+8)} matching m16n8k16 A layout.
        uint32_t phi[4][4], plo[4][4];
        float rs0 = 0.f, rs1 = 0.f;
#pragma unroll
        for (int nt = 0; nt < 8; nt++) {
            float p0 = exp2f(sacc[nt][0] - nm0);
            float p1 = exp2f(sacc[nt][1] - nm0);
            float p2 = exp2f(sacc[nt][2] - nm1);
            float p3 = exp2f(sacc[nt][3] - nm1);
            rs0 += p0 + p1; rs1 += p2 + p3;
            const int ks = nt >> 1, half = (nt & 1) * 2;
            bfsplit2(p0, p1, phi[ks][half],     plo[ks][half]);
            bfsplit2(p2, p3, phi[ks][half + 1], plo[ks][half + 1]);
        }
        rs0 += __shfl_xor_sync(0xffffffffu, rs0, 1);
        rs0 += __shfl_xor_sync(0xffffffffu, rs0, 2);
        rs1 += __shfl_xor_sync(0xffffffffu, rs1, 1);
        rs1 += __shfl_xor_sync(0xffffffffu, rs1, 2);
        l0 = l0 * corr0 + rs0;
        l1 = l1 * corr1 + rs1;

#pragma unroll
        for (int nt = 0; nt < 8; nt++) {
            oacc[nt][0] *= corr0; oacc[nt][1] *= corr0;
            oacc[nt][2] *= corr1; oacc[nt][3] *= corr1;
        }

        // --- O += P V, bf16x3 (4 k16 steps over s), P from registers ---
#pragma unroll
        for (int ks = 0; ks < 4; ks++) {
            const int p0 = 8 * ks + tg;
#pragma unroll
            for (int nt = 0; nt < 8; nt++) {
                const int br = (nt * 8 + g) * FSP;
                uint32_t vh[2] = { Vth[br + p0], Vth[br + p0 + 4] };
                uint32_t vl[2] = { Vtl[br + p0], Vtl[br + p0 + 4] };
                mma16(oacc[nt], phi[ks], vh);
                mma16(oacc[nt], phi[ks], vl);
                mma16(oacc[nt], plo[ks], vh);
            }
        }
    }

    // --- epilogue: normalize, store [T][D] ---
    const float inv0 = 1.0f / l0, inv1 = 1.0f / l1;
#pragma unroll
    for (int nt = 0; nt < 8; nt++) {
        const int cb = hcol + nt * 8 + 2 * tg;
        *(float2*)&out[(size_t)(q0 + row0) * D_DIM + cb] =
            make_float2(oacc[nt][0] * inv0, oacc[nt][1] * inv0);
        *(float2*)&out[(size_t)(q0 + row0 + 8) * D_DIM + cb] =
            make_float2(oacc[nt][2] * inv1, oacc[nt][3] * inv1);
    }
}

// ---------------------------------------------------------------------------
extern "C" void kernel_launch(void* const* d_in, const int* in_sizes, int n_in,
                              void* d_out, int out_size) {
    const float* x     = (const float*)d_in[0];  // [4096,1024]
    const float* Wqkv  = (const float*)d_in[1];  // [3072,1024]
    const float* Wproj = (const float*)d_in[2];  // [1024,1024]
    float* out = (float*)d_out;                  // [4096,1024]

    float* qkv; cudaGetSymbolAddress((void**)&qkv, g_qkv);
    float* att; cudaGetSymbolAddress((void**)&att, g_att);

    cudaFuncSetAttribute(flash_attn_tc, cudaFuncAttributeMaxDynamicSharedMemorySize, FA_SMEM);

    // 1) qkv = x @ W_qkv^T
    dim3 g1((3 * D_DIM) / 128, T_DIM / 128);
    gemm_mma_bf16x3<<<g1, 256>>>(x, Wqkv, qkv, T_DIM, 3 * D_DIM, D_DIM);

    // 2) RoPE in place on q, k
    int total = T_DIM * H_NUM * (C_DIM / 2);
    rope_kernel<<<(total + 255) / 256, 256>>>(qkv);

    // 3) causal flash attention (bf16x3 tensor cores, P in registers) -> att
    dim3 g2(T_DIM / 128, H_NUM);
    flash_attn_tc<<<g2, 256, FA_SMEM>>>(qkv, att);

    // 4) out = att @ W_proj^T
    dim3 g3(D_DIM / 128, T_DIM / 128);
    gemm_mma_bf16x3<<<g3, 256>>>(att, Wproj, out, T_DIM, D_DIM, D_DIM);
}

// round 15
// speedup vs baseline: 2.2013x; 1.1232x over previous
#include <cuda_runtime.h>
#include <cuda_bf16.h>
#include <math.h>
#include <stdint.h>

#define T_DIM 4096
#define D_DIM 1024
#define H_NUM 16
#define C_DIM 64
#define SP   12   // gemm plane row stride (8 bf16-pairs + 4 pad), uint32 units
#define FSP  36   // flash plane row stride (32 bf16-pairs + 4 pad), uint32 units

// Scratch (allocations forbidden -> device globals)
__device__ float g_qkv[T_DIM * 3 * D_DIM];   // [T][3*D]
__device__ float g_att[T_DIM * D_DIM];       // [T][D]

// ---------------------------------------------------------------------------
// helpers
// ---------------------------------------------------------------------------
__device__ __forceinline__ uint32_t bfpack(float a, float b) {
    __nv_bfloat162 t = __floats2bfloat162_rn(a, b);   // low half = a (k-even)
    return *(uint32_t*)&t;
}
__device__ __forceinline__ void bfsplit2(float a, float b, uint32_t& hi, uint32_t& lo) {
    float ha = __bfloat162float(__float2bfloat16_rn(a));
    float hb = __bfloat162float(__float2bfloat16_rn(b));
    hi = bfpack(ha, hb);
    lo = bfpack(a - ha, b - hb);
}
__device__ __forceinline__ void mma16(float* d, const uint32_t* a, const uint32_t* b) {
    asm volatile(
        "mma.sync.aligned.m16n8k16.row.col.f32.bf16.bf16.f32 "
        "{%0,%1,%2,%3}, {%4,%5,%6,%7}, {%8,%9}, {%0,%1,%2,%3};"
        : "+f"(d[0]), "+f"(d[1]), "+f"(d[2]), "+f"(d[3])
        : "r"(a[0]), "r"(a[1]), "r"(a[2]), "r"(a[3]), "r"(b[0]), "r"(b[1]));
}
__device__ __forceinline__ uint32_t smemu(const void* p) {
    return (uint32_t)__cvta_generic_to_shared(p);
}
#define LDSM4(r0, r1, r2, r3, addr)                                         \
    asm volatile("ldmatrix.sync.aligned.m8n8.x4.shared.b16 {%0,%1,%2,%3}, [%4];" \
                 : "=r"(r0), "=r"(r1), "=r"(r2), "=r"(r3) : "r"(addr))

// ===========================================================================
// mma.sync bf16x3 GEMM (single buffer, R12 structure) + ldmatrix frag loads.
// 128x128 CTA tile, K-chunk 16, 256 threads, 8 warps 64x32, 2 CTAs/SM.
// Fragment loads: A = 8 LDSM.x4 (4 mt x hi/lo), B = 4 LDSM.x4 per chunk
// (was 48 scalar LDS). Bank-clean: 8 rows at stride 12 words cover all banks.
// ===========================================================================
__global__ void __launch_bounds__(256, 2) gemm_mma_bf16x3(
    const float* __restrict__ A, const float* __restrict__ B, float* __restrict__ C,
    int M, int N, int K)
{
    __shared__ uint32_t sAh[128 * SP];
    __shared__ uint32_t sAl[128 * SP];
    __shared__ uint32_t sBh[128 * SP];
    __shared__ uint32_t sBl[128 * SP];

    const int tid  = threadIdx.x;
    const int lane = tid & 31;
    const int g    = lane >> 2;
    const int tg   = lane & 3;
    const int wid  = tid >> 5;
    const int wm   = wid >> 2;
    const int wn   = wid & 3;
    const int bm   = blockIdx.y * 128;
    const int bn   = blockIdx.x * 128;

    // loader: 4 threads per row, 4 floats each (chunk = 16 floats/row)
    const int r0g = (tid + 0)   >> 2, c0g = ((tid + 0)   & 3) * 4;
    const int r1g = (tid + 256) >> 2, c1g = ((tid + 256) & 3) * 4;
    const float* A0 = A + (size_t)(bm + r0g) * K + c0g;
    const float* A1 = A + (size_t)(bm + r1g) * K + c1g;
    const float* B0 = B + (size_t)(bn + r0g) * K + c0g;
    const float* B1 = B + (size_t)(bn + r1g) * K + c1g;
    const int sa0 = r0g * SP + (c0g >> 1), sa1 = r1g * SP + (c1g >> 1);

    // ldmatrix lane address offsets (bytes)
    const uint32_t a_off = (uint32_t)((wm * 64 + (lane & 15)) * SP) * 4 + ((lane >> 4) << 4);
    const uint32_t b_off = (uint32_t)((wn * 32 + ((lane >> 4) << 3) + (lane & 7)) * SP) * 4
                         + (((lane >> 3) & 1) << 4);
    const uint32_t ah_b = smemu(sAh) + a_off, al_b = smemu(sAl) + a_off;
    const uint32_t bh_b = smemu(sBh) + b_off, bl_b = smemu(sBl) + b_off;

    float acc[4][4][4];
#pragma unroll
    for (int i = 0; i < 4; i++)
#pragma unroll
        for (int j = 0; j < 4; j++)
#pragma unroll
            for (int k = 0; k < 4; k++) acc[i][j][k] = 0.f;

    const int nch = K >> 4;
    float4 ra0 = *(const float4*)A0, ra1 = *(const float4*)A1;
    float4 rb0 = *(const float4*)B0, rb1 = *(const float4*)B1;

    for (int c = 0; c < nch; c++) {
        {
            uint32_t h, l;
            bfsplit2(ra0.x, ra0.y, h, l); sAh[sa0]     = h; sAl[sa0]     = l;
            bfsplit2(ra0.z, ra0.w, h, l); sAh[sa0 + 1] = h; sAl[sa0 + 1] = l;
            bfsplit2(ra1.x, ra1.y, h, l); sAh[sa1]     = h; sAl[sa1]     = l;
            bfsplit2(ra1.z, ra1.w, h, l); sAh[sa1 + 1] = h; sAl[sa1 + 1] = l;
            bfsplit2(rb0.x, rb0.y, h, l); sBh[sa0]     = h; sBl[sa0]     = l;
            bfsplit2(rb0.z, rb0.w, h, l); sBh[sa0 + 1] = h; sBl[sa0 + 1] = l;
            bfsplit2(rb1.x, rb1.y, h, l); sBh[sa1]     = h; sBl[sa1]     = l;
            bfsplit2(rb1.z, rb1.w, h, l); sBh[sa1 + 1] = h; sBl[sa1 + 1] = l;
        }
        __syncthreads();

        if (c + 1 < nch) {
            const int off = (c + 1) * 16;
            ra0 = *(const float4*)(A0 + off); ra1 = *(const float4*)(A1 + off);
            rb0 = *(const float4*)(B0 + off); rb1 = *(const float4*)(B1 + off);
        }

        {
            uint32_t ah[4][4], al[4][4], bh[4][2], bl[4][2];
#pragma unroll
            for (int mt = 0; mt < 4; mt++) {
                const uint32_t mo = (uint32_t)(mt * 16 * SP) * 4;
                LDSM4(ah[mt][0], ah[mt][1], ah[mt][2], ah[mt][3], ah_b + mo);
                LDSM4(al[mt][0], al[mt][1], al[mt][2], al[mt][3], al_b + mo);
            }
#pragma unroll
            for (int p = 0; p < 2; p++) {
                const uint32_t po = (uint32_t)(p * 16 * SP) * 4;
                LDSM4(bh[2 * p][0], bh[2 * p][1], bh[2 * p + 1][0], bh[2 * p + 1][1], bh_b + po);
                LDSM4(bl[2 * p][0], bl[2 * p][1], bl[2 * p + 1][0], bl[2 * p + 1][1], bl_b + po);
            }
#pragma unroll
            for (int mt = 0; mt < 4; mt++)
#pragma unroll
                for (int nt = 0; nt < 4; nt++) {
                    mma16(acc[mt][nt], ah[mt], bh[nt]);
                    mma16(acc[mt][nt], ah[mt], bl[nt]);
                    mma16(acc[mt][nt], al[mt], bh[nt]);
                }
        }
        __syncthreads();
    }

#pragma unroll
    for (int mt = 0; mt < 4; mt++) {
        const int row = bm + wm * 64 + mt * 16 + g;
#pragma unroll
        for (int nt = 0; nt < 4; nt++) {
            const int col = bn + wn * 32 + nt * 8 + 2 * tg;
            *(float2*)&C[(size_t)row * N + col] =
                make_float2(acc[mt][nt][0], acc[mt][nt][1]);
            *(float2*)&C[(size_t)(row + 8) * N + col] =
                make_float2(acc[mt][nt][2], acc[mt][nt][3]);
        }
    }
}

// ---------------------------------------------------------------------------
// RoPE in place on q,k inside g_qkv [T][3*D]
// ---------------------------------------------------------------------------
__global__ void rope_kernel(float* __restrict__ qkv) {
    int idx = blockIdx.x * blockDim.x + threadIdx.x;
    if (idx >= T_DIM * H_NUM * (C_DIM / 2)) return;
    int t = idx >> 9;
    int r = idx & 511;
    int h = r >> 5;
    int p = r & 31;

    float inv_freq = expf(-(float)p * (logf(10000.0f) / 32.0f));
    float ang = (float)t * inv_freq;
    float s, c;
    sincosf(ang, &s, &c);

    size_t base_q = (size_t)t * (3 * D_DIM) + h * C_DIM + 2 * p;
    size_t base_k = base_q + D_DIM;

    float x1 = qkv[base_q], x2 = qkv[base_q + 1];
    qkv[base_q]     = x1 * c - x2 * s;
    qkv[base_q + 1] = x2 * c + x1 * s;

    float y1 = qkv[base_k], y2 = qkv[base_k + 1];
    qkv[base_k]     = y1 * c - y2 * s;
    qkv[base_k + 1] = y2 * c + y1 * s;
}

// ===========================================================================
// Tensor-core flash attention, bf16x3 (m16n8k16), causal, ldmatrix frags.
// Bq=128, Bk=64, C=64, 256 threads / 8 warps, 2 CTAs/SM.
// P stays in registers (accumulator layout == A-fragment layout over s).
// Q a-frags: 2 LDSM/ks; K/V b-frags: 8 LDSM/ks (was 24 scalar LDS).
// Smem: Q,K,V planes only = 73,728 B.
// ===========================================================================
#define FA_SMEM ((2 * 128 + 2 * 64 + 2 * 64) * FSP * 4)
#define SC2 0.18033688f   // 0.125 * log2(e)

__global__ void __launch_bounds__(256, 2) flash_attn_tc(
    const float* __restrict__ qkv, float* __restrict__ out)
{
    extern __shared__ uint32_t smu[];
    uint32_t* Qh  = smu;
    uint32_t* Ql  = Qh  + 128 * FSP;
    uint32_t* Kh  = Ql  + 128 * FSP;
    uint32_t* Kl  = Kh  + 64 * FSP;
    uint32_t* Vth = Kl  + 64 * FSP;   // V^T: row=c, pairs over s
    uint32_t* Vtl = Vth + 64 * FSP;

    const int h    = blockIdx.y;
    const int qb   = gridDim.x - 1 - blockIdx.x;   // big blocks first
    const int q0   = qb * 128;
    const int tid  = threadIdx.x;
    const int lane = tid & 31;
    const int g    = lane >> 2;
    const int tg   = lane & 3;
    const int wid  = tid >> 5;
    const int hcol = h * C_DIM;
    const int row0 = wid * 16 + g;                 // local S/O row of c0,c1

    // loader mappings
    const int kr   = tid >> 4;          // K/Q row base (idx=tid+256i -> row kr+16i)
    const int kc4  = (tid & 15) * 4;    // K/Q col group (4 floats = 2 pairs)
    const int vc   = tid & 63;          // V column (head dim c) -> V^T row
    const int vr4  = (tid >> 6) * 4;    // V s-chunk base

    // ldmatrix lane address offsets (bytes)
    const uint32_t a_off = (uint32_t)((wid * 16 + (lane & 15)) * FSP) * 4 + ((lane >> 4) << 4);
    const uint32_t b_off = (uint32_t)((((lane >> 4) << 3) + (lane & 7)) * FSP) * 4
                         + (((lane >> 3) & 1) << 4);
    const uint32_t qh_b = smemu(Qh)  + a_off, ql_b = smemu(Ql)  + a_off;
    const uint32_t kh_b = smemu(Kh)  + b_off, kl_b = smemu(Kl)  + b_off;
    const uint32_t vh_b = smemu(Vth) + b_off, vl_b = smemu(Vtl) + b_off;

    // --- load Q tile [128][64], split to bf16 hi/lo pair planes ---
#pragma unroll
    for (int i = 0; i < 8; i++) {
        int idx = tid + 256 * i;
        int r = idx >> 4, c4 = (idx & 15) * 4;
        float4 v = *(const float4*)&qkv[(size_t)(q0 + r) * (3 * D_DIM) + hcol + c4];
        uint32_t hh, ll;
        int sa = r * FSP + (c4 >> 1);
        bfsplit2(v.x, v.y, hh, ll); Qh[sa]     = hh; Ql[sa]     = ll;
        bfsplit2(v.z, v.w, hh, ll); Qh[sa + 1] = hh; Ql[sa + 1] = ll;
    }

    float m0 = -1e30f, m1 = -1e30f, l0 = 0.f, l1 = 0.f;
    float oacc[8][4];
#pragma unroll
    for (int nt = 0; nt < 8; nt++)
#pragma unroll
        for (int j = 0; j < 4; j++) oacc[nt][j] = 0.f;

    const float* kbase = qkv + 1024 + hcol + (size_t)kr * (3 * D_DIM) + kc4;
    const float* vbase = qkv + 2048 + hcol + vc;

    const int kbmax = 2 * qb + 1;
    for (int kb = 0; kb <= kbmax; kb++) {
        __syncthreads();  // all warps done reading prior K/V smem

        // --- load K/V tile from gmem, split to smem planes ---
        {
            const size_t off = (size_t)kb * 64 * (3 * D_DIM);
#pragma unroll
            for (int i = 0; i < 4; i++) {
                const int r = kr + 16 * i;
                float4 kv = *(const float4*)(kbase + off + (size_t)(16 * i) * (3 * D_DIM));
                uint32_t hh, ll;
                int ka = r * FSP + (kc4 >> 1);
                bfsplit2(kv.x, kv.y, hh, ll); Kh[ka]     = hh; Kl[ka]     = ll;
                bfsplit2(kv.z, kv.w, hh, ll); Kh[ka + 1] = hh; Kl[ka + 1] = ll;

                float v0 = vbase[off + (size_t)(vr4 + 16 * i + 0) * (3 * D_DIM)];
                float v1 = vbase[off + (size_t)(vr4 + 16 * i + 1) * (3 * D_DIM)];
                float v2 = vbase[off + (size_t)(vr4 + 16 * i + 2) * (3 * D_DIM)];
                float v3 = vbase[off + (size_t)(vr4 + 16 * i + 3) * (3 * D_DIM)];
                int va = vc * FSP + ((vr4 + 16 * i) >> 1);
                bfsplit2(v0, v1, hh, ll); Vth[va]     = hh; Vtl[va]     = ll;
                bfsplit2(v2, v3, hh, ll); Vth[va + 1] = hh; Vtl[va + 1] = ll;
            }
        }
        __syncthreads();

        // --- S = Q K^T, bf16x3 (4 k16 steps), ldmatrix frags ---
        float sacc[8][4];
#pragma unroll
        for (int nt = 0; nt < 8; nt++)
#pragma unroll
            for (int j = 0; j < 4; j++) sacc[nt][j] = 0.f;

#pragma unroll
        for (int ks = 0; ks < 4; ks++) {
            const uint32_t ko = (uint32_t)ks << 5;   // 8 pairs = 32 bytes per k16
            uint32_t ah[4], al[4];
            LDSM4(ah[0], ah[1], ah[2], ah[3], qh_b + ko);
            LDSM4(al[0], al[1], al[2], al[3], ql_b + ko);
#pragma unroll
            for (int p = 0; p < 4; p++) {
                const uint32_t po = (uint32_t)(p * 16 * FSP) * 4 + ko;
                uint32_t bh[2][2], bl[2][2];
                LDSM4(bh[0][0], bh[0][1], bh[1][0], bh[1][1], kh_b + po);
                LDSM4(bl[0][0], bl[0][1], bl[1][0], bl[1][1], kl_b + po);
                mma16(sacc[2 * p],     ah, bh[0]);
                mma16(sacc[2 * p],     ah, bl[0]);
                mma16(sacc[2 * p],     al, bh[0]);
                mma16(sacc[2 * p + 1], ah, bh[1]);
                mma16(sacc[2 * p + 1], ah, bl[1]);
                mma16(sacc[2 * p + 1], al, bh[1]);
            }
        }

        // --- scale (log2 domain) + causal mask ---
        const bool mb = (kb >= 2 * qb);
        const int lim = q0 - kb * 64;   // keep col c if c <= row + lim
        float mx0 = -1e30f, mx1 = -1e30f;
#pragma unroll
        for (int nt = 0; nt < 8; nt++) {
            const int cb = nt * 8 + 2 * tg;
#pragma unroll
            for (int j = 0; j < 2; j++) {
                float v0 = sacc[nt][j] * SC2;
                float v1 = sacc[nt][2 + j] * SC2;
                if (mb) {
                    if (cb + j > row0 + lim)     v0 = -1e30f;
                    if (cb + j > row0 + 8 + lim) v1 = -1e30f;
                }
                sacc[nt][j] = v0; sacc[nt][2 + j] = v1;
                mx0 = fmaxf(mx0, v0); mx1 = fmaxf(mx1, v1);
            }
        }
        mx0 = fmaxf(mx0, __shfl_xor_sync(0xffffffffu, mx0, 1));
        mx0 = fmaxf(mx0, __shfl_xor_sync(0xffffffffu, mx0, 2));
        mx1 = fmaxf(mx1, __shfl_xor_sync(0xffffffffu, mx1, 1));
        mx1 = fmaxf(mx1, __shfl_xor_sync(0xffffffffu, mx1, 2));

        const float nm0 = fmaxf(m0, mx0), nm1 = fmaxf(m1, mx1);
        const float corr0 = exp2f(m0 - nm0), corr1 = exp2f(m1 - nm1);
        m0 = nm0; m1 = nm1;

        // --- softmax -> P packed DIRECTLY into PV A-fragments (no smem) ---
        uint32_t phi[4][4], plo[4][4];
        float rs0 = 0.f, rs1 = 0.f;
#pragma unroll
        for (int nt = 0; nt < 8; nt++) {
            float p0 = exp2f(sacc[nt][0] - nm0);
            float p1 = exp2f(sacc[nt][1] - nm0);
            float p2 = exp2f(sacc[nt][2] - nm1);
            float p3 = exp2f(sacc[nt][3] - nm1);
            rs0 += p0 + p1; rs1 += p2 + p3;
            const int ks = nt >> 1, half = (nt & 1) * 2;
            bfsplit2(p0, p1, phi[ks][half],     plo[ks][half]);
            bfsplit2(p2, p3, phi[ks][half + 1], plo[ks][half + 1]);
        }
        rs0 += __shfl_xor_sync(0xffffffffu, rs0, 1);
        rs0 += __shfl_xor_sync(0xffffffffu, rs0, 2);
        rs1 += __shfl_xor_sync(0xffffffffu, rs1, 1);
        rs1 += __shfl_xor_sync(0xffffffffu, rs1, 2);
        l0 = l0 * corr0 + rs0;
        l1 = l1 * corr1 + rs1;

#pragma unroll
        for (int nt = 0; nt < 8; nt++) {
            oacc[nt][0] *= corr0; oacc[nt][1] *= corr0;
            oacc[nt][2] *= corr1; oacc[nt][3] *= corr1;
        }

        // --- O += P V, bf16x3 (4 k16 steps over s), P regs + V ldmatrix ---
#pragma unroll
        for (int ks = 0; ks < 4; ks++) {
            const uint32_t ko = (uint32_t)ks << 5;
#pragma unroll
            for (int p = 0; p < 4; p++) {
                const uint32_t po = (uint32_t)(p * 16 * FSP) * 4 + ko;
                uint32_t vh[2][2], vl[2][2];
                LDSM4(vh[0][0], vh[0][1], vh[1][0], vh[1][1], vh_b + po);
                LDSM4(vl[0][0], vl[0][1], vl[1][0], vl[1][1], vl_b + po);
                mma16(oacc[2 * p],     phi[ks], vh[0]);
                mma16(oacc[2 * p],     phi[ks], vl[0]);
                mma16(oacc[2 * p],     plo[ks], vh[0]);
                mma16(oacc[2 * p + 1], phi[ks], vh[1]);
                mma16(oacc[2 * p + 1], phi[ks], vl[1]);
                mma16(oacc[2 * p + 1], plo[ks], vh[1]);
            }
        }
    }

    // --- epilogue: normalize, store [T][D] ---
    const float inv0 = 1.0f / l0, inv1 = 1.0f / l1;
#pragma unroll
    for (int nt = 0; nt < 8; nt++) {
        const int cb = hcol + nt * 8 + 2 * tg;
        *(float2*)&out[(size_t)(q0 + row0) * D_DIM + cb] =
            make_float2(oacc[nt][0] * inv0, oacc[nt][1] * inv0);
        *(float2*)&out[(size_t)(q0 + row0 + 8) * D_DIM + cb] =
            make_float2(oacc[nt][2] * inv1, oacc[nt][3] * inv1);
    }
}

// ---------------------------------------------------------------------------
extern "C" void kernel_launch(void* const* d_in, const int* in_sizes, int n_in,
                              void* d_out, int out_size) {
    const float* x     = (const float*)d_in[0];  // [4096,1024]
    const float* Wqkv  = (const float*)d_in[1];  // [3072,1024]
    const float* Wproj = (const float*)d_in[2];  // [1024,1024]
    float* out = (float*)d_out;                  // [4096,1024]

    float* qkv; cudaGetSymbolAddress((void**)&qkv, g_qkv);
    float* att; cudaGetSymbolAddress((void**)&att, g_att);

    cudaFuncSetAttribute(flash_attn_tc, cudaFuncAttributeMaxDynamicSharedMemorySize, FA_SMEM);

    // 1) qkv = x @ W_qkv^T
    dim3 g1((3 * D_DIM) / 128, T_DIM / 128);
    gemm_mma_bf16x3<<<g1, 256>>>(x, Wqkv, qkv, T_DIM, 3 * D_DIM, D_DIM);

    // 2) RoPE in place on q, k
    int total = T_DIM * H_NUM * (C_DIM / 2);
    rope_kernel<<<(total + 255) / 256, 256>>>(qkv);

    // 3) causal flash attention (bf16x3, ldmatrix, P in regs) -> att
    dim3 g2(T_DIM / 128, H_NUM);
    flash_attn_tc<<<g2, 256, FA_SMEM>>>(qkv, att);

    // 4) out = att @ W_proj^T
    dim3 g3(D_DIM / 128, T_DIM / 128);
    gemm_mma_bf16x3<<<g3, 256>>>(att, Wproj, out, T_DIM, D_DIM, D_DIM);
}

// round 16
// speedup vs baseline: 2.5043x; 1.1377x over previous
#include <cuda_runtime.h>
#include <cuda_bf16.h>
#include <math.h>
#include <stdint.h>

#define T_DIM 4096
#define D_DIM 1024
#define H_NUM 16
#define C_DIM 64
#define SP2  20   // gemm plane row stride (16 bf16-pairs + 4 pad), uint32 units
#define FSP  36   // flash plane row stride (32 bf16-pairs + 4 pad), uint32 units

// Scratch (allocations forbidden -> device globals)
__device__ float g_qkv[T_DIM * 3 * D_DIM];   // [T][3*D]
__device__ float g_att[T_DIM * D_DIM];       // [T][D]

// ---------------------------------------------------------------------------
// helpers
// ---------------------------------------------------------------------------
__device__ __forceinline__ uint32_t bfpack(float a, float b) {
    __nv_bfloat162 t = __floats2bfloat162_rn(a, b);   // low half = a (k-even)
    return *(uint32_t*)&t;
}
__device__ __forceinline__ void bfsplit2(float a, float b, uint32_t& hi, uint32_t& lo) {
    float ha = __bfloat162float(__float2bfloat16_rn(a));
    float hb = __bfloat162float(__float2bfloat16_rn(b));
    hi = bfpack(ha, hb);
    lo = bfpack(a - ha, b - hb);
}
__device__ __forceinline__ void mma16(float* d, const uint32_t* a, const uint32_t* b) {
    asm volatile(
        "mma.sync.aligned.m16n8k16.row.col.f32.bf16.bf16.f32 "
        "{%0,%1,%2,%3}, {%4,%5,%6,%7}, {%8,%9}, {%0,%1,%2,%3};"
        : "+f"(d[0]), "+f"(d[1]), "+f"(d[2]), "+f"(d[3])
        : "r"(a[0]), "r"(a[1]), "r"(a[2]), "r"(a[3]), "r"(b[0]), "r"(b[1]));
}
__device__ __forceinline__ uint32_t smemu(const void* p) {
    return (uint32_t)__cvta_generic_to_shared(p);
}
#define LDSM4(r0, r1, r2, r3, addr)                                         \
    asm volatile("ldmatrix.sync.aligned.m8n8.x4.shared.b16 {%0,%1,%2,%3}, [%4];" \
                 : "=r"(r0), "=r"(r1), "=r"(r2), "=r"(r3) : "r"(addr))

// ===========================================================================
// mma.sync bf16x3 GEMM, K-chunk 32 (2 k16 sub-steps per barrier pair).
// 128x128 CTA tile, 256 threads, 8 warps 64x32, 2 CTAs/SM, ldmatrix frags.
// Halves barrier crossings vs chunk-16 (96 mma per load/sync phase).
// Direct gmem->split->smem in store phase (MLP=8; co-CTA hides latency).
// ===========================================================================
__global__ void __launch_bounds__(256, 2) gemm_mma_bf16x3(
    const float* __restrict__ A, const float* __restrict__ B, float* __restrict__ C,
    int M, int N, int K)
{
    __shared__ uint32_t sAh[128 * SP2];
    __shared__ uint32_t sAl[128 * SP2];
    __shared__ uint32_t sBh[128 * SP2];
    __shared__ uint32_t sBl[128 * SP2];

    const int tid  = threadIdx.x;
    const int lane = tid & 31;
    const int g    = lane >> 2;
    const int tg   = lane & 3;
    const int wid  = tid >> 5;
    const int wm   = wid >> 2;
    const int wn   = wid & 3;
    const int bm   = blockIdx.y * 128;
    const int bn   = blockIdx.x * 128;

    // loader: 8 threads per row, 4 floats each; rows r+32i, i=0..3
    const int lr = tid >> 3;            // 0..31
    const int lc = (tid & 7) * 4;       // 0..28
    const float* A0 = A + (size_t)(bm + lr) * K + lc;
    const float* B0 = B + (size_t)(bn + lr) * K + lc;
    const int sbase = lr * SP2 + (lc >> 1);

    // ldmatrix lane address offsets (bytes)
    const uint32_t a_off = (uint32_t)((wm * 64 + (lane & 15)) * SP2) * 4 + ((lane >> 4) << 4);
    const uint32_t b_off = (uint32_t)((wn * 32 + ((lane >> 4) << 3) + (lane & 7)) * SP2) * 4
                         + (((lane >> 3) & 1) << 4);
    const uint32_t ah_b = smemu(sAh) + a_off, al_b = smemu(sAl) + a_off;
    const uint32_t bh_b = smemu(sBh) + b_off, bl_b = smemu(sBl) + b_off;

    float acc[4][4][4];
#pragma unroll
    for (int i = 0; i < 4; i++)
#pragma unroll
        for (int j = 0; j < 4; j++)
#pragma unroll
            for (int k = 0; k < 4; k++) acc[i][j][k] = 0.f;

    const int nch = K >> 5;   // K/32

    for (int c = 0; c < nch; c++) {
        // --- load + split + store chunk c ---
        {
            const int koff = c * 32;
#pragma unroll
            for (int i = 0; i < 4; i++) {
                const size_t ro = (size_t)(32 * i) * K + koff;
                const int sa = sbase + 32 * i * SP2;
                float4 va = *(const float4*)(A0 + ro);
                float4 vb = *(const float4*)(B0 + ro);
                uint32_t h, l;
                bfsplit2(va.x, va.y, h, l); sAh[sa]     = h; sAl[sa]     = l;
                bfsplit2(va.z, va.w, h, l); sAh[sa + 1] = h; sAl[sa + 1] = l;
                bfsplit2(vb.x, vb.y, h, l); sBh[sa]     = h; sBl[sa]     = l;
                bfsplit2(vb.z, vb.w, h, l); sBh[sa + 1] = h; sBl[sa + 1] = l;
            }
        }
        __syncthreads();

        // --- compute: 2 k16 sub-steps ---
#pragma unroll
        for (int ks = 0; ks < 2; ks++) {
            const uint32_t ko = (uint32_t)ks << 5;   // 8 pairs = 32 bytes
            uint32_t ah[4][4], al[4][4], bh[4][2], bl[4][2];
#pragma unroll
            for (int mt = 0; mt < 4; mt++) {
                const uint32_t mo = (uint32_t)(mt * 16 * SP2) * 4 + ko;
                LDSM4(ah[mt][0], ah[mt][1], ah[mt][2], ah[mt][3], ah_b + mo);
                LDSM4(al[mt][0], al[mt][1], al[mt][2], al[mt][3], al_b + mo);
            }
#pragma unroll
            for (int p = 0; p < 2; p++) {
                const uint32_t po = (uint32_t)(p * 16 * SP2) * 4 + ko;
                LDSM4(bh[2 * p][0], bh[2 * p][1], bh[2 * p + 1][0], bh[2 * p + 1][1], bh_b + po);
                LDSM4(bl[2 * p][0], bl[2 * p][1], bl[2 * p + 1][0], bl[2 * p + 1][1], bl_b + po);
            }
#pragma unroll
            for (int mt = 0; mt < 4; mt++)
#pragma unroll
                for (int nt = 0; nt < 4; nt++) {
                    mma16(acc[mt][nt], ah[mt], bh[nt]);
                    mma16(acc[mt][nt], ah[mt], bl[nt]);
                    mma16(acc[mt][nt], al[mt], bh[nt]);
                }
        }
        __syncthreads();
    }

#pragma unroll
    for (int mt = 0; mt < 4; mt++) {
        const int row = bm + wm * 64 + mt * 16 + g;
#pragma unroll
        for (int nt = 0; nt < 4; nt++) {
            const int col = bn + wn * 32 + nt * 8 + 2 * tg;
            *(float2*)&C[(size_t)row * N + col] =
                make_float2(acc[mt][nt][0], acc[mt][nt][1]);
            *(float2*)&C[(size_t)(row + 8) * N + col] =
                make_float2(acc[mt][nt][2], acc[mt][nt][3]);
        }
    }
}

// ---------------------------------------------------------------------------
// RoPE in place on q,k inside g_qkv [T][3*D]
// ---------------------------------------------------------------------------
__global__ void rope_kernel(float* __restrict__ qkv) {
    int idx = blockIdx.x * blockDim.x + threadIdx.x;
    if (idx >= T_DIM * H_NUM * (C_DIM / 2)) return;
    int t = idx >> 9;
    int r = idx & 511;
    int h = r >> 5;
    int p = r & 31;

    float inv_freq = expf(-(float)p * (logf(10000.0f) / 32.0f));
    float ang = (float)t * inv_freq;
    float s, c;
    sincosf(ang, &s, &c);

    size_t base_q = (size_t)t * (3 * D_DIM) + h * C_DIM + 2 * p;
    size_t base_k = base_q + D_DIM;

    float x1 = qkv[base_q], x2 = qkv[base_q + 1];
    qkv[base_q]     = x1 * c - x2 * s;
    qkv[base_q + 1] = x2 * c + x1 * s;

    float y1 = qkv[base_k], y2 = qkv[base_k + 1];
    qkv[base_k]     = y1 * c - y2 * s;
    qkv[base_k + 1] = y2 * c + y1 * s;
}

// ===========================================================================
// Tensor-core flash attention, bf16x3, causal, ldmatrix, P in registers.
// qb-PAIRED: CTA x=i processes q-tiles qb=i then qb=31-i -> uniform 68
// kv-block units per CTA, single balanced wave (256 CTAs, 2/SM).
// ===========================================================================
#define FA_SMEM ((2 * 128 + 2 * 64 + 2 * 64) * FSP * 4)
#define SC2 0.18033688f   // 0.125 * log2(e)

__global__ void __launch_bounds__(256, 2) flash_attn_tc(
    const float* __restrict__ qkv, float* __restrict__ out)
{
    extern __shared__ uint32_t smu[];
    uint32_t* Qh  = smu;
    uint32_t* Ql  = Qh  + 128 * FSP;
    uint32_t* Kh  = Ql  + 128 * FSP;
    uint32_t* Kl  = Kh  + 64 * FSP;
    uint32_t* Vth = Kl  + 64 * FSP;   // V^T: row=c, pairs over s
    uint32_t* Vtl = Vth + 64 * FSP;

    const int h    = blockIdx.y;
    const int tid  = threadIdx.x;
    const int lane = tid & 31;
    const int g    = lane >> 2;
    const int tg   = lane & 3;
    const int wid  = tid >> 5;
    const int hcol = h * C_DIM;
    const int row0 = wid * 16 + g;

    const int kr   = tid >> 4;
    const int kc4  = (tid & 15) * 4;
    const int vc   = tid & 63;
    const int vr4  = (tid >> 6) * 4;

    const uint32_t a_off = (uint32_t)((wid * 16 + (lane & 15)) * FSP) * 4 + ((lane >> 4) << 4);
    const uint32_t b_off = (uint32_t)((((lane >> 4) << 3) + (lane & 7)) * FSP) * 4
                         + (((lane >> 3) & 1) << 4);
    const uint32_t qh_b = smemu(Qh)  + a_off, ql_b = smemu(Ql)  + a_off;
    const uint32_t kh_b = smemu(Kh)  + b_off, kl_b = smemu(Kl)  + b_off;
    const uint32_t vh_b = smemu(Vth) + b_off, vl_b = smemu(Vtl) + b_off;

    const float* kbase = qkv + 1024 + hcol + (size_t)kr * (3 * D_DIM) + kc4;
    const float* vbase = qkv + 2048 + hcol + vc;

#pragma unroll 1
    for (int half = 0; half < 2; half++) {
        const int qb = half ? (31 - (int)blockIdx.x) : (int)blockIdx.x;
        const int q0 = qb * 128;

        __syncthreads();   // prior tile's smem reads fully drained

        // --- load Q tile [128][64], split to bf16 hi/lo pair planes ---
#pragma unroll
        for (int i = 0; i < 8; i++) {
            int idx = tid + 256 * i;
            int r = idx >> 4, c4 = (idx & 15) * 4;
            float4 v = *(const float4*)&qkv[(size_t)(q0 + r) * (3 * D_DIM) + hcol + c4];
            uint32_t hh, ll;
            int sa = r * FSP + (c4 >> 1);
            bfsplit2(v.x, v.y, hh, ll); Qh[sa]     = hh; Ql[sa]     = ll;
            bfsplit2(v.z, v.w, hh, ll); Qh[sa + 1] = hh; Ql[sa + 1] = ll;
        }

        float m0 = -1e30f, m1 = -1e30f, l0 = 0.f, l1 = 0.f;
        float oacc[8][4];
#pragma unroll
        for (int nt = 0; nt < 8; nt++)
#pragma unroll
            for (int j = 0; j < 4; j++) oacc[nt][j] = 0.f;

        const int kbmax = 2 * qb + 1;
        for (int kb = 0; kb <= kbmax; kb++) {
            __syncthreads();  // all warps done reading prior K/V smem (+ Q visible)

            // --- load K/V tile from gmem, split to smem planes ---
            {
                const size_t off = (size_t)kb * 64 * (3 * D_DIM);
#pragma unroll
                for (int i = 0; i < 4; i++) {
                    const int r = kr + 16 * i;
                    float4 kv = *(const float4*)(kbase + off + (size_t)(16 * i) * (3 * D_DIM));
                    uint32_t hh, ll;
                    int ka = r * FSP + (kc4 >> 1);
                    bfsplit2(kv.x, kv.y, hh, ll); Kh[ka]     = hh; Kl[ka]     = ll;
                    bfsplit2(kv.z, kv.w, hh, ll); Kh[ka + 1] = hh; Kl[ka + 1] = ll;

                    float v0 = vbase[off + (size_t)(vr4 + 16 * i + 0) * (3 * D_DIM)];
                    float v1 = vbase[off + (size_t)(vr4 + 16 * i + 1) * (3 * D_DIM)];
                    float v2 = vbase[off + (size_t)(vr4 + 16 * i + 2) * (3 * D_DIM)];
                    float v3 = vbase[off + (size_t)(vr4 + 16 * i + 3) * (3 * D_DIM)];
                    int va = vc * FSP + ((vr4 + 16 * i) >> 1);
                    bfsplit2(v0, v1, hh, ll); Vth[va]     = hh; Vtl[va]     = ll;
                    bfsplit2(v2, v3, hh, ll); Vth[va + 1] = hh; Vtl[va + 1] = ll;
                }
            }
            __syncthreads();

            // --- S = Q K^T, bf16x3 (4 k16 steps), ldmatrix frags ---
            float sacc[8][4];
#pragma unroll
            for (int nt = 0; nt < 8; nt++)
#pragma unroll
                for (int j = 0; j < 4; j++) sacc[nt][j] = 0.f;

#pragma unroll
            for (int ks = 0; ks < 4; ks++) {
                const uint32_t ko = (uint32_t)ks << 5;
                uint32_t ah[4], al[4];
                LDSM4(ah[0], ah[1], ah[2], ah[3], qh_b + ko);
                LDSM4(al[0], al[1], al[2], al[3], ql_b + ko);
#pragma unroll
                for (int p = 0; p < 4; p++) {
                    const uint32_t po = (uint32_t)(p * 16 * FSP) * 4 + ko;
                    uint32_t bh[2][2], bl[2][2];
                    LDSM4(bh[0][0], bh[0][1], bh[1][0], bh[1][1], kh_b + po);
                    LDSM4(bl[0][0], bl[0][1], bl[1][0], bl[1][1], kl_b + po);
                    mma16(sacc[2 * p],     ah, bh[0]);
                    mma16(sacc[2 * p],     ah, bl[0]);
                    mma16(sacc[2 * p],     al, bh[0]);
                    mma16(sacc[2 * p + 1], ah, bh[1]);
                    mma16(sacc[2 * p + 1], ah, bl[1]);
                    mma16(sacc[2 * p + 1], al, bh[1]);
                }
            }

            // --- scale (log2 domain) + causal mask ---
            const bool mb = (kb >= 2 * qb);
            const int lim = q0 - kb * 64;
            float mx0 = -1e30f, mx1 = -1e30f;
#pragma unroll
            for (int nt = 0; nt < 8; nt++) {
                const int cb = nt * 8 + 2 * tg;
#pragma unroll
                for (int j = 0; j < 2; j++) {
                    float v0 = sacc[nt][j] * SC2;
                    float v1 = sacc[nt][2 + j] * SC2;
                    if (mb) {
                        if (cb + j > row0 + lim)     v0 = -1e30f;
                        if (cb + j > row0 + 8 + lim) v1 = -1e30f;
                    }
                    sacc[nt][j] = v0; sacc[nt][2 + j] = v1;
                    mx0 = fmaxf(mx0, v0); mx1 = fmaxf(mx1, v1);
                }
            }
            mx0 = fmaxf(mx0, __shfl_xor_sync(0xffffffffu, mx0, 1));
            mx0 = fmaxf(mx0, __shfl_xor_sync(0xffffffffu, mx0, 2));
            mx1 = fmaxf(mx1, __shfl_xor_sync(0xffffffffu, mx1, 1));
            mx1 = fmaxf(mx1, __shfl_xor_sync(0xffffffffu, mx1, 2));

            const float nm0 = fmaxf(m0, mx0), nm1 = fmaxf(m1, mx1);
            const float corr0 = exp2f(m0 - nm0), corr1 = exp2f(m1 - nm1);
            m0 = nm0; m1 = nm1;

            // --- softmax -> P packed directly into PV A-fragments ---
            uint32_t phi[4][4], plo[4][4];
            float rs0 = 0.f, rs1 = 0.f;
#pragma unroll
            for (int nt = 0; nt < 8; nt++) {
                float p0 = exp2f(sacc[nt][0] - nm0);
                float p1 = exp2f(sacc[nt][1] - nm0);
                float p2 = exp2f(sacc[nt][2] - nm1);
                float p3 = exp2f(sacc[nt][3] - nm1);
                rs0 += p0 + p1; rs1 += p2 + p3;
                const int ks = nt >> 1, hf = (nt & 1) * 2;
                bfsplit2(p0, p1, phi[ks][hf],     plo[ks][hf]);
                bfsplit2(p2, p3, phi[ks][hf + 1], plo[ks][hf + 1]);
            }
            rs0 += __shfl_xor_sync(0xffffffffu, rs0, 1);
            rs0 += __shfl_xor_sync(0xffffffffu, rs0, 2);
            rs1 += __shfl_xor_sync(0xffffffffu, rs1, 1);
            rs1 += __shfl_xor_sync(0xffffffffu, rs1, 2);
            l0 = l0 * corr0 + rs0;
            l1 = l1 * corr1 + rs1;

#pragma unroll
            for (int nt = 0; nt < 8; nt++) {
                oacc[nt][0] *= corr0; oacc[nt][1] *= corr0;
                oacc[nt][2] *= corr1; oacc[nt][3] *= corr1;
            }

            // --- O += P V, bf16x3, P from registers + V ldmatrix ---
#pragma unroll
            for (int ks = 0; ks < 4; ks++) {
                const uint32_t ko = (uint32_t)ks << 5;
#pragma unroll
                for (int p = 0; p < 4; p++) {
                    const uint32_t po = (uint32_t)(p * 16 * FSP) * 4 + ko;
                    uint32_t vh[2][2], vl[2][2];
                    LDSM4(vh[0][0], vh[0][1], vh[1][0], vh[1][1], vh_b + po);
                    LDSM4(vl[0][0], vl[0][1], vl[1][0], vl[1][1], vl_b + po);
                    mma16(oacc[2 * p],     phi[ks], vh[0]);
                    mma16(oacc[2 * p],     phi[ks], vl[0]);
                    mma16(oacc[2 * p],     plo[ks], vh[0]);
                    mma16(oacc[2 * p + 1], phi[ks], vh[1]);
                    mma16(oacc[2 * p + 1], phi[ks], vl[1]);
                    mma16(oacc[2 * p + 1], plo[ks], vh[1]);
                }
            }
        }

        // --- epilogue: normalize, store [T][D] ---
        const float inv0 = 1.0f / l0, inv1 = 1.0f / l1;
#pragma unroll
        for (int nt = 0; nt < 8; nt++) {
            const int cb = hcol + nt * 8 + 2 * tg;
            *(float2*)&out[(size_t)(q0 + row0) * D_DIM + cb] =
                make_float2(oacc[nt][0] * inv0, oacc[nt][1] * inv0);
            *(float2*)&out[(size_t)(q0 + row0 + 8) * D_DIM + cb] =
                make_float2(oacc[nt][2] * inv1, oacc[nt][3] * inv1);
        }
    }
}

// ---------------------------------------------------------------------------
extern "C" void kernel_launch(void* const* d_in, const int* in_sizes, int n_in,
                              void* d_out, int out_size) {
    const float* x     = (const float*)d_in[0];  // [4096,1024]
    const float* Wqkv  = (const float*)d_in[1];  // [3072,1024]
    const float* Wproj = (const float*)d_in[2];  // [1024,1024]
    float* out = (float*)d_out;                  // [4096,1024]

    float* qkv; cudaGetSymbolAddress((void**)&qkv, g_qkv);
    float* att; cudaGetSymbolAddress((void**)&att, g_att);

    cudaFuncSetAttribute(flash_attn_tc, cudaFuncAttributeMaxDynamicSharedMemorySize, FA_SMEM);

    // 1) qkv = x @ W_qkv^T
    dim3 g1((3 * D_DIM) / 128, T_DIM / 128);
    gemm_mma_bf16x3<<<g1, 256>>>(x, Wqkv, qkv, T_DIM, 3 * D_DIM, D_DIM);

    // 2) RoPE in place on q, k
    int total = T_DIM * H_NUM * (C_DIM / 2);
    rope_kernel<<<(total + 255) / 256, 256>>>(qkv);

    // 3) causal flash attention (bf16x3, ldmatrix, P in regs, qb-paired)
    dim3 g2(16, H_NUM);
    flash_attn_tc<<<g2, 256, FA_SMEM>>>(qkv, att);

    // 4) out = att @ W_proj^T
    dim3 g3(D_DIM / 128, T_DIM / 128);
    gemm_mma_bf16x3<<<g3, 256>>>(att, Wproj, out, T_DIM, D_DIM, D_DIM);
}